// round 13
// baseline (speedup 1.0000x reference)
#include <cuda_runtime.h>
#include <cuda_bf16.h>
#include <cstdint>
#include <math.h>

// ---------------- problem constants ----------------
#define DD    1024
#define NHEADS 16
#define HDIM  64
#define BSZ   2
#define TT    16
#define LLEN  256
#define MTOK  8192          // B*T*L
#define HFF   2730
#define HFFP  2752          // padded (= 43*64)
#define W12P  5504          // 2*HFFP interleaved output width
#define QKVN  3072
#define MODN  9216          // 9*D
#define NPERS 296           // persistent GEMM grid (148 SMs x 2 CTA)

// ---------------- device scratch (allocation-free rule) ----------------
__device__ float g_X  [(size_t)MTOK * DD];
__device__ float g_MODS[BSZ * MODN];
__device__ float g_SC  [BSZ * DD];
__device__ float g_W12B[W12P];
// bf16 buffers
__device__ __nv_bfloat16 g_QKV[(size_t)MTOK * QKVN];
__device__ __nv_bfloat16 g_XN [(size_t)MTOK * DD];
__device__ __nv_bfloat16 g_ATT[(size_t)MTOK * DD];
__device__ __nv_bfloat16 g_H  [(size_t)MTOK * HFFP];
__device__ __nv_bfloat16 g_W3P[(size_t)DD * HFFP];
__device__ __nv_bfloat16 g_WQS[(size_t)QKVN * DD];
__device__ __nv_bfloat16 g_WPS[(size_t)DD * DD];
__device__ __nv_bfloat16 g_WQT[(size_t)QKVN * DD];
__device__ __nv_bfloat16 g_WPT[(size_t)DD * DD];
__device__ __nv_bfloat16 g_W12I[(size_t)W12P * DD];

// ---------------- PTX helpers ----------------
__device__ __forceinline__ void cp16(uint32_t s, const void* g) {
    asm volatile("cp.async.cg.shared.global [%0], [%1], 16;\n" :: "r"(s), "l"(g));
}
__device__ __forceinline__ void cp16z(uint32_t s, const void* g, int sz) {
    asm volatile("cp.async.cg.shared.global [%0], [%1], 16, %2;\n" :: "r"(s), "l"(g), "r"(sz));
}
__device__ __forceinline__ void cp_commit() { asm volatile("cp.async.commit_group;\n"); }
__device__ __forceinline__ void cp_wait1()  { asm volatile("cp.async.wait_group 1;\n"); }

#define LDSM4(r0, r1, r2, r3, addr) \
    asm volatile("ldmatrix.sync.aligned.m8n8.x4.shared.b16 {%0,%1,%2,%3}, [%4];" \
        : "=r"(r0), "=r"(r1), "=r"(r2), "=r"(r3) : "r"(addr))

typedef unsigned long long u64t;
__device__ __forceinline__ u64t pk2(float lo, float hi) {
    u64t r; asm("mov.b64 %0, {%1,%2};" : "=l"(r) : "f"(lo), "f"(hi)); return r;
}
__device__ __forceinline__ u64t fma2_(u64t a, u64t b, u64t c) {
    u64t d; asm("fma.rn.f32x2 %0,%1,%2,%3;" : "=l"(d) : "l"(a), "l"(b), "l"(c)); return d;
}
__device__ __forceinline__ float2 upk2(u64t v) {
    float2 f; asm("mov.b64 {%0,%1}, %2;" : "=f"(f.x), "=f"(f.y) : "l"(v)); return f;
}
// 4 consecutive bf16 (as uint2) -> float4
__device__ __forceinline__ float4 bf4_to_f4(uint2 u) {
    __nv_bfloat162 a = *reinterpret_cast<__nv_bfloat162*>(&u.x);
    __nv_bfloat162 b = *reinterpret_cast<__nv_bfloat162*>(&u.y);
    float2 fa = __bfloat1622float2(a);
    float2 fb = __bfloat1622float2(b);
    return make_float4(fa.x, fa.y, fb.x, fb.y);
}

// ---------------- small utility kernels ----------------
__global__ void tobf16_kernel(const float4* __restrict__ src, __nv_bfloat162* __restrict__ dst, int n4) {
    int i = blockIdx.x * 256 + threadIdx.x;
    if (i < n4) {
        float4 v = src[i];
        dst[2 * i]     = __floats2bfloat162_rn(v.x, v.y);
        dst[2 * i + 1] = __floats2bfloat162_rn(v.z, v.w);
    }
}

__global__ void siluc_kernel(const float* __restrict__ c, float* __restrict__ out) {
    int i = blockIdx.x * 256 + threadIdx.x;
    if (i < BSZ * DD) {
        float v = c[i];
        out[i] = v / (1.f + expf(-v));
    }
}

// mods = silu(c) @ ada_w.T + ada_b   -> (B, 9*D)   (tiny, fp32 exact)
__global__ void mods_kernel(const float* __restrict__ sc, const float* __restrict__ aw,
                            const float* __restrict__ ab, float* __restrict__ mods) {
    int gw = (blockIdx.x * blockDim.x + threadIdx.x) >> 5;
    int lane = threadIdx.x & 31;
    if (gw >= BSZ * MODN) return;
    int b = gw / MODN, n = gw % MODN;
    const float4* cv = (const float4*)(sc + b * DD);
    const float4* wv = (const float4*)(aw + (size_t)n * DD);
    float s = 0.f;
#pragma unroll
    for (int k = 0; k < 8; k++) {
        float4 a = cv[lane + k * 32];
        float4 w = wv[lane + k * 32];
        s += a.x * w.x + a.y * w.y + a.z * w.z + a.w * w.w;
    }
#pragma unroll
    for (int o = 16; o > 0; o >>= 1) s += __shfl_down_sync(0xffffffffu, s, o);
    if (lane == 0) mods[gw] = s + ab[n];
}

__global__ void padw3_kernel(const float* __restrict__ w3, __nv_bfloat162* __restrict__ w3p) {
    int idx = blockIdx.x * 256 + threadIdx.x;      // over DD * HFFP/2
    if (idx >= DD * (HFFP / 2)) return;
    int n = idx / (HFFP / 2), kp = idx % (HFFP / 2);
    int k = kp * 2;
    float a = (k < HFF) ? w3[(size_t)n * HFF + k] : 0.f;
    float b = (k < HFF) ? w3[(size_t)n * HFF + k + 1] : 0.f;
    w3p[idx] = __floats2bfloat162_rn(a, b);
}

// interleaved W12: out column 2j -> w12 row j (h1), 2j+1 -> row HFF+j (h2); pad j>=HFF with 0
__global__ void w12prep_kernel(const float* __restrict__ w12w, const float* __restrict__ w12b,
                               __nv_bfloat162* __restrict__ W12I, float* __restrict__ BI) {
    int idx = blockIdx.x * 256 + threadIdx.x;      // over W12P * DD / 2
    if (idx >= W12P * (DD / 2)) return;
    int n = idx / (DD / 2);
    int k = (idx % (DD / 2)) * 2;
    int j = n >> 1, s = n & 1;
    float a = 0.f, b = 0.f;
    if (j < HFF) {
        const float* src = w12w + (size_t)(j + s * HFF) * DD + k;
        a = src[0]; b = src[1];
    }
    W12I[idx] = __floats2bfloat162_rn(a, b);
    if (k == 0) BI[n] = (j < HFF) ? w12b[j + s * HFF] : 0.f;
}

// rmsnorm + adaLN modulation -> bf16
__global__ void rmsnorm_mod_kernel(const float* __restrict__ X, __nv_bfloat16* __restrict__ XN,
                                   const float* __restrict__ w, const float* __restrict__ mods,
                                   int shIdx, int scIdx, int gatherT) {
    int m = blockIdx.x;
    int tid = threadIdx.x;
    int b = m >> 12;
    int srcRow = m;
    if (gatherT) {
        int rem = m & 4095;
        int l = rem >> 4;
        int t = rem & 15;
        srcRow = (b * TT + t) * LLEN + l;
    }
    float4 v = ((const float4*)(X + (size_t)srcRow * DD))[tid];
    float ss = v.x * v.x + v.y * v.y + v.z * v.z + v.w * v.w;
    __shared__ float red[8];
#pragma unroll
    for (int o = 16; o > 0; o >>= 1) ss += __shfl_down_sync(0xffffffffu, ss, o);
    if ((tid & 31) == 0) red[tid >> 5] = ss;
    __syncthreads();
    float tot = red[0] + red[1] + red[2] + red[3] + red[4] + red[5] + red[6] + red[7];
    float r = rsqrtf(tot * (1.f / 1024.f) + 1e-6f);
    int d = tid * 4;
    const float* sh = mods + (b * 9 + shIdx) * DD;
    const float* sc = mods + (b * 9 + scIdx) * DD;
    float o0 = v.x * r * w[d + 0] * (1.f + sc[d + 0]) + sh[d + 0];
    float o1 = v.y * r * w[d + 1] * (1.f + sc[d + 1]) + sh[d + 1];
    float o2 = v.z * r * w[d + 2] * (1.f + sc[d + 2]) + sh[d + 2];
    float o3 = v.w * r * w[d + 3] * (1.f + sc[d + 3]) + sh[d + 3];
    __nv_bfloat162* row = (__nv_bfloat162*)(XN + (size_t)m * DD);
    row[2 * tid]     = __floats2bfloat162_rn(o0, o1);
    row[2 * tid + 1] = __floats2bfloat162_rn(o2, o3);
}

// ---------------- attention: fused qk-rmsnorm + RoPE, plain-exp softmax ----------------
template <int SEQ, int BH>
__global__ __launch_bounds__(256, 1) void attn_kernel(const __nv_bfloat16* __restrict__ QKV,
                                                      __nv_bfloat16* __restrict__ ATT,
                                                      const float* __restrict__ qw,
                                                      const float* __restrict__ kw,
                                                      const float* __restrict__ ct,
                                                      const float* __restrict__ st) {
    extern __shared__ float4 sm4[];
    float4* ks = sm4;                      // [BH][SEQ][16]
    float4* vs = sm4 + BH * SEQ * 16;
    int tid = threadIdx.x;
    int unit0 = blockIdx.x * BH;

    for (int i = tid; i < BH * SEQ * 16; i += 256) {
        int u = i / (SEQ * 16);
        int rem = i % (SEQ * 16);
        int j = rem / 16, d4 = rem % 16;
        int bh = unit0 + u;
        int batch = bh >> 4, head = bh & 15;
        const __nv_bfloat16* base = QKV + (size_t)(batch * SEQ + j) * QKVN + head * HDIM;
        const uint2* kp = (const uint2*)(base + DD);
        const uint2* vp = (const uint2*)(base + 2 * DD);
        ks[i] = bf4_to_f4(kp[d4]);
        vs[i] = bf4_to_f4(vp[d4]);
    }
    __syncthreads();

    // ---- K rows: rmsnorm(kw) + rope, in SMEM (1 row per thread) ----
    {
        float4* kr = ks + tid * 16;
        int posk = tid % SEQ;
        float4 kv[16];
        float s = 0.f;
#pragma unroll
        for (int i = 0; i < 16; i++) {
            kv[i] = kr[i];
            s += kv[i].x * kv[i].x + kv[i].y * kv[i].y + kv[i].z * kv[i].z + kv[i].w * kv[i].w;
        }
        float r = rsqrtf(s * (1.f / 64.f) + 1e-6f);
        const float4* w4 = (const float4*)kw;
        const float4* c4 = (const float4*)(ct + posk * 64);
        const float4* s4 = (const float4*)(st + posk * 64);
        float4 kn[16];
#pragma unroll
        for (int i = 0; i < 16; i++) {
            float4 ww = w4[i];
            kn[i] = make_float4(kv[i].x * r * ww.x, kv[i].y * r * ww.y,
                                kv[i].z * r * ww.z, kv[i].w * r * ww.w);
        }
#pragma unroll
        for (int i = 0; i < 8; i++) {
            float4 ca = c4[i], sa = s4[i], cb = c4[i + 8], sb = s4[i + 8];
            float4 lo = kn[i], hi = kn[i + 8];
            kr[i]     = make_float4(lo.x * ca.x - hi.x * sa.x, lo.y * ca.y - hi.y * sa.y,
                                    lo.z * ca.z - hi.z * sa.z, lo.w * ca.w - hi.w * sa.w);
            kr[i + 8] = make_float4(hi.x * cb.x + lo.x * sb.x, hi.y * cb.y + lo.y * sb.y,
                                    hi.z * cb.z + lo.z * sb.z, hi.w * cb.w + lo.w * sb.w);
        }
    }
    __syncthreads();

    int u = tid / SEQ, qi = tid % SEQ;
    int bh = unit0 + u;
    int batch = bh >> 4, head = bh & 15;
    const uint2* qp = (const uint2*)(QKV + (size_t)(batch * SEQ + qi) * QKVN + head * HDIM);
    u64t q2[32];
    {
        float4 q[16];
        float s = 0.f;
#pragma unroll
        for (int i = 0; i < 16; i++) {
            q[i] = bf4_to_f4(qp[i]);
            s += q[i].x * q[i].x + q[i].y * q[i].y + q[i].z * q[i].z + q[i].w * q[i].w;
        }
        float r = rsqrtf(s * (1.f / 64.f) + 1e-6f);
        const float4* w4 = (const float4*)qw;
        const float4* c4 = (const float4*)(ct + qi * 64);
        const float4* s4 = (const float4*)(st + qi * 64);
        float4 qn[16];
#pragma unroll
        for (int i = 0; i < 16; i++) {
            float4 ww = w4[i];
            qn[i] = make_float4(q[i].x * r * ww.x, q[i].y * r * ww.y,
                                q[i].z * r * ww.z, q[i].w * r * ww.w);
        }
#pragma unroll
        for (int i = 0; i < 8; i++) {
            float4 ca = c4[i], sa = s4[i], cb = c4[i + 8], sb = s4[i + 8];
            float4 lo = qn[i], hi = qn[i + 8];
            float4 e0 = make_float4(lo.x * ca.x - hi.x * sa.x, lo.y * ca.y - hi.y * sa.y,
                                    lo.z * ca.z - hi.z * sa.z, lo.w * ca.w - hi.w * sa.w);
            float4 e1 = make_float4(hi.x * cb.x + lo.x * sb.x, hi.y * cb.y + lo.y * sb.y,
                                    hi.z * cb.z + lo.z * sb.z, hi.w * cb.w + lo.w * sb.w);
            q2[2 * i]          = pk2(e0.x, e0.y);
            q2[2 * i + 1]      = pk2(e0.z, e0.w);
            q2[2 * (i + 8)]     = pk2(e1.x, e1.y);
            q2[2 * (i + 8) + 1] = pk2(e1.z, e1.w);
        }
    }

    const u64t z2 = pk2(0.f, 0.f);
    u64t o2[32];
#pragma unroll
    for (int i = 0; i < 32; i++) o2[i] = z2;

    float lsum = 0.f;
    const double2* kr2 = (const double2*)(ks + u * SEQ * 16);   // 16B vectors
    const double2* vr2 = (const double2*)(vs + u * SEQ * 16);
    for (int j = 0; j < SEQ; j++) {
        const double2* kj = kr2 + j * 16;
        u64t a0 = z2, a1 = z2, a2 = z2, a3 = z2;
#pragma unroll
        for (int i = 0; i < 8; i++) {
            double2 t0 = kj[2 * i];
            double2 t1 = kj[2 * i + 1];
            a0 = fma2_(q2[4 * i + 0], (u64t)__double_as_longlong(t0.x), a0);
            a1 = fma2_(q2[4 * i + 1], (u64t)__double_as_longlong(t0.y), a1);
            a2 = fma2_(q2[4 * i + 2], (u64t)__double_as_longlong(t1.x), a2);
            a3 = fma2_(q2[4 * i + 3], (u64t)__double_as_longlong(t1.y), a3);
        }
        float2 f0 = upk2(a0), f1 = upk2(a1), f2 = upk2(a2), f3 = upk2(a3);
        float s = ((f0.x + f0.y) + (f1.x + f1.y)) + ((f2.x + f2.y) + (f3.x + f3.y));
        float p = __expf(s * 0.125f);
        lsum += p;
        u64t p2 = pk2(p, p);
        const double2* vj = vr2 + j * 16;
#pragma unroll
        for (int i = 0; i < 16; i++) {
            double2 t = vj[i];
            o2[2 * i]     = fma2_(p2, (u64t)__double_as_longlong(t.x), o2[2 * i]);
            o2[2 * i + 1] = fma2_(p2, (u64t)__double_as_longlong(t.y), o2[2 * i + 1]);
        }
    }
    float inv = 1.f / lsum;
    __nv_bfloat162* op = (__nv_bfloat162*)(ATT + (size_t)(batch * SEQ + qi) * DD + head * HDIM);
#pragma unroll
    for (int i = 0; i < 32; i++) {
        float2 f = upk2(o2[i]);
        op[i] = __floats2bfloat162_rn(f.x * inv, f.y * inv);
    }
}

// ---------------- persistent bf16 GEMM with CONTINUOUS cp.async ring ----------------
// One stream of K-stages across all tiles owned by the CTA: no pipeline drain at
// tile switches; epilogue overlaps the next tile's loads.
// EPI 1: C[m,n] = resid[m,n] + gate[b,n]*(acc+bias)     (N==1024)
// EPI 2: like 1, scattered through (B,L,T)->(B,T,L)      (N==1024)
// EPI 3: fused SiLU-GLU: pairs (2j,2j+1)=(h1,h2) -> bf16 H[m,j], row stride HFFP
// EPI 4: bf16 output with bias (QKV)
#define BG_STG 10240           // 128 rows * 80 bytes (32 bf16 data + 8 pad)
#define BG_B_OFF (3 * BG_STG)  // 30720
#define BG_SMEM (6 * BG_STG)   // 61440

template <int EPI>
__global__ __launch_bounds__(128, 2) void bgemm(const __nv_bfloat16* __restrict__ A,
                                                const __nv_bfloat16* __restrict__ Bw,
                                                const float* __restrict__ bias,
                                                float* __restrict__ C,
                                                const float* __restrict__ resid,
                                                const float* __restrict__ gate,
                                                int M, int N, int K) {
    extern __shared__ char smem[];
    const int tid = threadIdx.x;
    const int wid = tid >> 5, lane = tid & 31;
    const int g = lane >> 2, t = lane & 3;
    const int wm0 = (wid >> 1) * 64, wn0 = (wid & 1) * 64;

    const uint32_t smemBase = (uint32_t)__cvta_generic_to_shared(smem);
    const uint32_t aBase = smemBase + tid * 80;
    const uint32_t bBase = aBase + BG_B_OFF;
    const uint32_t aFrag = smemBase + (wm0 + (lane & 15)) * 80 + (lane >> 4) * 16;
    const uint32_t bFrag = smemBase + BG_B_OFF
                         + (wn0 + (lane & 7) + ((lane >> 4) & 1) * 8) * 80
                         + ((lane >> 3) & 1) * 16;

    const int ntN = (N + 127) >> 7;
    const int ntiles = K >> 5;
    const int total = ntN * (M >> 7);
    const int nw = (total - blockIdx.x + gridDim.x - 1) / gridDim.x;  // tiles for this CTA (>=1 here)
    const int S = nw * ntiles;

    // ---- prefetch cursor ----
    int ptile = blockIdx.x;
    int pk = 0;
    const __nv_bfloat16* paRow;
    const __nv_bfloat16* pbRow;
    int pbsz;
    {
        int pm0 = (ptile / ntN) << 7, pn0 = (ptile % ntN) << 7;
        paRow = A + (size_t)(pm0 + tid) * K;
        int pgn = pn0 + tid;
        pbRow = Bw + (size_t)(pgn < N ? pgn : 0) * K;
        pbsz = (pgn < N) ? 16 : 0;
    }

    // ---- compute cursor ----
    int ctile = blockIdx.x;
    int ck = 0;
    int cm0 = (ctile / ntN) << 7, cn0 = (ctile % ntN) << 7;

    float acc[4][8][4];
#pragma unroll
    for (int i = 0; i < 4; i++)
#pragma unroll
        for (int j = 0; j < 8; j++)
#pragma unroll
            for (int r = 0; r < 4; r++) acc[i][j][r] = 0.f;

    // prologue: issue stages 0,1
#pragma unroll
    for (int p = 0; p < 2; p++) {
        int kt = pk << 5;
        uint32_t slot = p * BG_STG;
#pragma unroll
        for (int q = 0; q < 4; q++) cp16(aBase + slot + q * 16, paRow + kt + q * 8);
#pragma unroll
        for (int q = 0; q < 4; q++) cp16z(bBase + slot + q * 16, pbRow + kt + q * 8, pbsz);
        cp_commit();
        pk++;   // ntiles >= 32, no wrap possible here
    }

    for (int s = 0; s < S; s++) {
        cp_wait1();
        __syncthreads();

        // issue stage s+2 into slot (s+2)%3 (continuous ring, crosses tile boundaries)
        if (s + 2 < S) {
            int slotB = ((s + 2) % 3) * BG_STG;
            int kt = pk << 5;
#pragma unroll
            for (int q = 0; q < 4; q++) cp16(aBase + slotB + q * 16, paRow + kt + q * 8);
#pragma unroll
            for (int q = 0; q < 4; q++) cp16z(bBase + slotB + q * 16, pbRow + kt + q * 8, pbsz);
            if (++pk == ntiles) {          // advance prefetch cursor to next tile
                pk = 0;
                ptile += gridDim.x;
                if (ptile < total) {
                    int pm0 = (ptile / ntN) << 7, pn0 = (ptile % ntN) << 7;
                    paRow = A + (size_t)(pm0 + tid) * K;
                    int pgn = pn0 + tid;
                    pbRow = Bw + (size_t)(pgn < N ? pgn : 0) * K;
                    pbsz = (pgn < N) ? 16 : 0;
                }
            }
        }
        cp_commit();

        // compute from slot s%3
        const uint32_t aS = aFrag + (s % 3) * BG_STG;
        const uint32_t bS = bFrag + (s % 3) * BG_STG;
#pragma unroll
        for (int ks = 0; ks < 2; ks++) {
            uint32_t a[4][4], b[8][2];
#pragma unroll
            for (int i = 0; i < 4; i++)
                LDSM4(a[i][0], a[i][1], a[i][2], a[i][3], aS + i * (16 * 80) + ks * 32);
#pragma unroll
            for (int jj = 0; jj < 4; jj++)
                LDSM4(b[2 * jj][0], b[2 * jj][1], b[2 * jj + 1][0], b[2 * jj + 1][1],
                      bS + jj * (16 * 80) + ks * 32);
#pragma unroll
            for (int i = 0; i < 4; i++)
#pragma unroll
                for (int j = 0; j < 8; j++) {
                    asm volatile(
                        "mma.sync.aligned.m16n8k16.row.col.f32.bf16.bf16.f32 "
                        "{%0,%1,%2,%3},{%4,%5,%6,%7},{%8,%9},{%0,%1,%2,%3};\n"
                        : "+f"(acc[i][j][0]), "+f"(acc[i][j][1]),
                          "+f"(acc[i][j][2]), "+f"(acc[i][j][3])
                        : "r"(a[i][0]), "r"(a[i][1]), "r"(a[i][2]), "r"(a[i][3]),
                          "r"(b[j][0]), "r"(b[j][1]));
                }
        }

        // tile finished? -> epilogue (overlaps already-issued loads of next tile)
        if (++ck == ntiles) {
#pragma unroll
            for (int i = 0; i < 4; i++) {
                int mr = cm0 + wm0 + 16 * i + g;
#pragma unroll
                for (int j = 0; j < 8; j++) {
                    int nc = cn0 + wn0 + 8 * j + 2 * t;
                    if (nc >= N) continue;
#pragma unroll
                    for (int h = 0; h < 2; h++) {
                        int m = mr + h * 8;
                        float v0 = acc[i][j][2 * h + 0] + bias[nc];
                        float v1 = acc[i][j][2 * h + 1] + bias[nc + 1];
                        if (EPI == 1) {
                            int b = m >> 12;
                            size_t idx = (size_t)m * N + nc;
                            float2 rr = *(const float2*)(resid + idx);
                            float g0 = gate[b * MODN + nc], g1 = gate[b * MODN + nc + 1];
                            *(float2*)(C + idx) = make_float2(rr.x + g0 * v0, rr.y + g1 * v1);
                        } else if (EPI == 2) {
                            int b = m >> 12;
                            int rem = m & 4095;
                            int l = rem >> 4;
                            int ti = rem & 15;
                            size_t idx = ((size_t)((b * TT + ti) * LLEN + l)) * N + nc;
                            float2 rr = *(const float2*)(resid + idx);
                            float g0 = gate[b * MODN + nc], g1 = gate[b * MODN + nc + 1];
                            *(float2*)(C + idx) = make_float2(rr.x + g0 * v0, rr.y + g1 * v1);
                        } else if (EPI == 3) {
                            int pj = nc >> 1;
                            float hh = 0.f;
                            if (pj < HFF) {
                                float e = __expf(-v0);
                                hh = __fdividef(v0, 1.f + e) * v1;
                            }
                            ((__nv_bfloat16*)C)[(size_t)m * HFFP + pj] = __float2bfloat16(hh);
                        } else {  // EPI == 4
                            ((__nv_bfloat162*)C)[((size_t)m * N + nc) >> 1] = __floats2bfloat162_rn(v0, v1);
                        }
                    }
                }
            }
            // reset for next tile
            ck = 0;
            ctile += gridDim.x;
            if (ctile < total) {
                cm0 = (ctile / ntN) << 7;
                cn0 = (ctile % ntN) << 7;
            }
#pragma unroll
            for (int i = 0; i < 4; i++)
#pragma unroll
                for (int j = 0; j < 8; j++)
#pragma unroll
                    for (int r = 0; r < 4; r++) acc[i][j][r] = 0.f;
        }
    }
}

// ---------------- host orchestration ----------------
extern "C" void kernel_launch(void* const* d_in, const int* in_sizes, int n_in,
                              void* d_out, int out_size) {
    const float* x       = (const float*)d_in[0];
    const float* c       = (const float*)d_in[1];
    const float* cos_s   = (const float*)d_in[2];
    const float* sin_s   = (const float*)d_in[3];
    const float* cos_t   = (const float*)d_in[4];
    const float* sin_t   = (const float*)d_in[5];
    const float* norm1_w = (const float*)d_in[6];
    const float* norm2_w = (const float*)d_in[7];
    const float* norm3_w = (const float*)d_in[8];
    const float* qkv_s_w = (const float*)d_in[9];
    const float* qkv_s_b = (const float*)d_in[10];
    const float* qn_s_w  = (const float*)d_in[11];
    const float* kn_s_w  = (const float*)d_in[12];
    const float* proj_s_w= (const float*)d_in[13];
    const float* proj_s_b= (const float*)d_in[14];
    const float* qkv_t_w = (const float*)d_in[15];
    const float* qkv_t_b = (const float*)d_in[16];
    const float* qn_t_w  = (const float*)d_in[17];
    const float* kn_t_w  = (const float*)d_in[18];
    const float* proj_t_w= (const float*)d_in[19];
    const float* proj_t_b= (const float*)d_in[20];
    const float* w12_w   = (const float*)d_in[21];
    const float* w12_b   = (const float*)d_in[22];
    const float* w3_w    = (const float*)d_in[23];
    const float* w3_b    = (const float*)d_in[24];
    const float* ada_w   = (const float*)d_in[25];
    const float* ada_b   = (const float*)d_in[26];
    float* out = (float*)d_out;

    float *X, *MODS, *SC, *W12B;
    __nv_bfloat16 *QKV, *XN, *ATT, *H, *W3P, *WQS, *WPS, *WQT, *WPT, *W12I;
    cudaGetSymbolAddress((void**)&X,   g_X);
    cudaGetSymbolAddress((void**)&MODS,g_MODS);
    cudaGetSymbolAddress((void**)&SC,  g_SC);
    cudaGetSymbolAddress((void**)&W12B,g_W12B);
    cudaGetSymbolAddress((void**)&QKV, g_QKV);
    cudaGetSymbolAddress((void**)&XN,  g_XN);
    cudaGetSymbolAddress((void**)&ATT, g_ATT);
    cudaGetSymbolAddress((void**)&H,   g_H);
    cudaGetSymbolAddress((void**)&W3P, g_W3P);
    cudaGetSymbolAddress((void**)&WQS, g_WQS);
    cudaGetSymbolAddress((void**)&WPS, g_WPS);
    cudaGetSymbolAddress((void**)&WQT, g_WQT);
    cudaGetSymbolAddress((void**)&WPT, g_WPT);
    cudaGetSymbolAddress((void**)&W12I,g_W12I);

    cudaFuncSetAttribute(attn_kernel<256, 1>, cudaFuncAttributeMaxDynamicSharedMemorySize, 131072);
    cudaFuncSetAttribute(attn_kernel<16, 16>, cudaFuncAttributeMaxDynamicSharedMemorySize, 131072);
    cudaFuncSetAttribute(bgemm<1>, cudaFuncAttributeMaxDynamicSharedMemorySize, BG_SMEM);
    cudaFuncSetAttribute(bgemm<2>, cudaFuncAttributeMaxDynamicSharedMemorySize, BG_SMEM);
    cudaFuncSetAttribute(bgemm<3>, cudaFuncAttributeMaxDynamicSharedMemorySize, BG_SMEM);
    cudaFuncSetAttribute(bgemm<4>, cudaFuncAttributeMaxDynamicSharedMemorySize, BG_SMEM);

    // init + weight conversion to bf16
    siluc_kernel<<<(BSZ * DD + 255) / 256, 256>>>(c, SC);
    mods_kernel<<<BSZ * MODN / 8, 256>>>(SC, ada_w, ada_b, MODS);
    tobf16_kernel<<<QKVN * DD / 4 / 256, 256>>>((const float4*)qkv_s_w, (__nv_bfloat162*)WQS, QKVN * DD / 4);
    tobf16_kernel<<<DD * DD / 4 / 256, 256>>>((const float4*)proj_s_w, (__nv_bfloat162*)WPS, DD * DD / 4);
    tobf16_kernel<<<QKVN * DD / 4 / 256, 256>>>((const float4*)qkv_t_w, (__nv_bfloat162*)WQT, QKVN * DD / 4);
    tobf16_kernel<<<DD * DD / 4 / 256, 256>>>((const float4*)proj_t_w, (__nv_bfloat162*)WPT, DD * DD / 4);
    w12prep_kernel<<<(W12P * DD / 2 + 255) / 256, 256>>>(w12_w, w12_b, (__nv_bfloat162*)W12I, W12B);
    padw3_kernel<<<(DD * HFFP / 2 + 255) / 256, 256>>>(w3_w, (__nv_bfloat162*)W3P);

    // ---- spatial attention branch (residual read straight from input x) ----
    rmsnorm_mod_kernel<<<MTOK, 256>>>(x, XN, norm1_w, MODS, 0, 1, 0);
    bgemm<4><<<NPERS, 128, BG_SMEM>>>(XN, WQS, qkv_s_b, (float*)QKV, nullptr, nullptr, MTOK, QKVN, DD);
    attn_kernel<256, 1><<<BSZ * TT * NHEADS, 256, 131072>>>(QKV, ATT, qn_s_w, kn_s_w, cos_s, sin_s);
    bgemm<1><<<NPERS, 128, BG_SMEM>>>(ATT, WPS, proj_s_b, X, x, MODS + 2 * DD, MTOK, DD, DD);

    // ---- temporal attention branch ----
    rmsnorm_mod_kernel<<<MTOK, 256>>>(X, XN, norm2_w, MODS, 3, 4, 1);
    bgemm<4><<<NPERS, 128, BG_SMEM>>>(XN, WQT, qkv_t_b, (float*)QKV, nullptr, nullptr, MTOK, QKVN, DD);
    attn_kernel<16, 16><<<BSZ * LLEN * NHEADS / 16, 256, 131072>>>(QKV, ATT, qn_t_w, kn_t_w, cos_t, sin_t);
    bgemm<2><<<NPERS, 128, BG_SMEM>>>(ATT, WPT, proj_t_b, X, X, MODS + 5 * DD, MTOK, DD, DD);

    // ---- MLP (SiLU-GLU fused into w12 GEMM epilogue) ----
    rmsnorm_mod_kernel<<<MTOK, 256>>>(X, XN, norm3_w, MODS, 6, 7, 0);
    bgemm<3><<<NPERS, 128, BG_SMEM>>>(XN, W12I, W12B, (float*)H, nullptr, nullptr, MTOK, W12P, DD);
    bgemm<1><<<NPERS, 128, BG_SMEM>>>(H, W3P, w3_b, out, X, MODS + 8 * DD, MTOK, DD, HFFP);
}

// round 14
// speedup vs baseline: 1.0620x; 1.0620x over previous
#include <cuda_runtime.h>
#include <cuda_bf16.h>
#include <cstdint>
#include <math.h>

// ---------------- problem constants ----------------
#define DD    1024
#define NHEADS 16
#define HDIM  64
#define BSZ   2
#define TT    16
#define LLEN  256
#define MTOK  8192          // B*T*L
#define HFF   2730
#define HFFP  2752          // padded (= 43*64)
#define W12P  5504          // 2*HFFP interleaved output width
#define QKVN  3072
#define MODN  9216          // 9*D

// ---------------- device scratch (allocation-free rule) ----------------
__device__ float g_X  [(size_t)MTOK * DD];
__device__ float g_MODS[BSZ * MODN];
__device__ float g_SC  [BSZ * DD];
__device__ float g_W12B[W12P];
// bf16 buffers
__device__ __nv_bfloat16 g_QKV[(size_t)MTOK * QKVN];
__device__ __nv_bfloat16 g_XN [(size_t)MTOK * DD];
__device__ __nv_bfloat16 g_ATT[(size_t)MTOK * DD];
__device__ __nv_bfloat16 g_H  [(size_t)MTOK * HFFP];
__device__ __nv_bfloat16 g_W3P[(size_t)DD * HFFP];
__device__ __nv_bfloat16 g_WQS[(size_t)QKVN * DD];
__device__ __nv_bfloat16 g_WPS[(size_t)DD * DD];
__device__ __nv_bfloat16 g_WQT[(size_t)QKVN * DD];
__device__ __nv_bfloat16 g_WPT[(size_t)DD * DD];
__device__ __nv_bfloat16 g_W12I[(size_t)W12P * DD];

// ---------------- PTX helpers ----------------
__device__ __forceinline__ void cp16(uint32_t s, const void* g) {
    asm volatile("cp.async.cg.shared.global [%0], [%1], 16;\n" :: "r"(s), "l"(g));
}
__device__ __forceinline__ void cp_commit() { asm volatile("cp.async.commit_group;\n"); }
__device__ __forceinline__ void cp_wait1()  { asm volatile("cp.async.wait_group 1;\n"); }

#define LDSM4(r0, r1, r2, r3, addr) \
    asm volatile("ldmatrix.sync.aligned.m8n8.x4.shared.b16 {%0,%1,%2,%3}, [%4];" \
        : "=r"(r0), "=r"(r1), "=r"(r2), "=r"(r3) : "r"(addr))

typedef unsigned long long u64t;
__device__ __forceinline__ u64t pk2(float lo, float hi) {
    u64t r; asm("mov.b64 %0, {%1,%2};" : "=l"(r) : "f"(lo), "f"(hi)); return r;
}
__device__ __forceinline__ u64t fma2_(u64t a, u64t b, u64t c) {
    u64t d; asm("fma.rn.f32x2 %0,%1,%2,%3;" : "=l"(d) : "l"(a), "l"(b), "l"(c)); return d;
}
__device__ __forceinline__ float2 upk2(u64t v) {
    float2 f; asm("mov.b64 {%0,%1}, %2;" : "=f"(f.x), "=f"(f.y) : "l"(v)); return f;
}
// 4 consecutive bf16 (as uint2) -> float4
__device__ __forceinline__ float4 bf4_to_f4(uint2 u) {
    __nv_bfloat162 a = *reinterpret_cast<__nv_bfloat162*>(&u.x);
    __nv_bfloat162 b = *reinterpret_cast<__nv_bfloat162*>(&u.y);
    float2 fa = __bfloat1622float2(a);
    float2 fb = __bfloat1622float2(b);
    return make_float4(fa.x, fa.y, fb.x, fb.y);
}

// ---------------- small utility kernels ----------------
__global__ void tobf16_kernel(const float4* __restrict__ src, __nv_bfloat162* __restrict__ dst, int n4) {
    int i = blockIdx.x * 256 + threadIdx.x;
    if (i < n4) {
        float4 v = src[i];
        dst[2 * i]     = __floats2bfloat162_rn(v.x, v.y);
        dst[2 * i + 1] = __floats2bfloat162_rn(v.z, v.w);
    }
}

__global__ void siluc_kernel(const float* __restrict__ c, float* __restrict__ out) {
    int i = blockIdx.x * 256 + threadIdx.x;
    if (i < BSZ * DD) {
        float v = c[i];
        out[i] = v / (1.f + expf(-v));
    }
}

// mods = silu(c) @ ada_w.T + ada_b   -> (B, 9*D)   (tiny, fp32 exact)
__global__ void mods_kernel(const float* __restrict__ sc, const float* __restrict__ aw,
                            const float* __restrict__ ab, float* __restrict__ mods) {
    int gw = (blockIdx.x * blockDim.x + threadIdx.x) >> 5;
    int lane = threadIdx.x & 31;
    if (gw >= BSZ * MODN) return;
    int b = gw / MODN, n = gw % MODN;
    const float4* cv = (const float4*)(sc + b * DD);
    const float4* wv = (const float4*)(aw + (size_t)n * DD);
    float s = 0.f;
#pragma unroll
    for (int k = 0; k < 8; k++) {
        float4 a = cv[lane + k * 32];
        float4 w = wv[lane + k * 32];
        s += a.x * w.x + a.y * w.y + a.z * w.z + a.w * w.w;
    }
#pragma unroll
    for (int o = 16; o > 0; o >>= 1) s += __shfl_down_sync(0xffffffffu, s, o);
    if (lane == 0) mods[gw] = s + ab[n];
}

__global__ void padw3_kernel(const float* __restrict__ w3, __nv_bfloat162* __restrict__ w3p) {
    int idx = blockIdx.x * 256 + threadIdx.x;      // over DD * HFFP/2
    if (idx >= DD * (HFFP / 2)) return;
    int n = idx / (HFFP / 2), kp = idx % (HFFP / 2);
    int k = kp * 2;
    float a = (k < HFF) ? w3[(size_t)n * HFF + k] : 0.f;
    float b = (k < HFF) ? w3[(size_t)n * HFF + k + 1] : 0.f;
    w3p[idx] = __floats2bfloat162_rn(a, b);
}

// interleaved W12: out column 2j -> w12 row j (h1), 2j+1 -> row HFF+j (h2); pad j>=HFF with 0
__global__ void w12prep_kernel(const float* __restrict__ w12w, const float* __restrict__ w12b,
                               __nv_bfloat162* __restrict__ W12I, float* __restrict__ BI) {
    int idx = blockIdx.x * 256 + threadIdx.x;      // over W12P * DD / 2
    if (idx >= W12P * (DD / 2)) return;
    int n = idx / (DD / 2);
    int k = (idx % (DD / 2)) * 2;
    int j = n >> 1, s = n & 1;
    float a = 0.f, b = 0.f;
    if (j < HFF) {
        const float* src = w12w + (size_t)(j + s * HFF) * DD + k;
        a = src[0]; b = src[1];
    }
    W12I[idx] = __floats2bfloat162_rn(a, b);
    if (k == 0) BI[n] = (j < HFF) ? w12b[j + s * HFF] : 0.f;
}

// rmsnorm + adaLN modulation -> bf16
__global__ void rmsnorm_mod_kernel(const float* __restrict__ X, __nv_bfloat16* __restrict__ XN,
                                   const float* __restrict__ w, const float* __restrict__ mods,
                                   int shIdx, int scIdx, int gatherT) {
    int m = blockIdx.x;
    int tid = threadIdx.x;
    int b = m >> 12;
    int srcRow = m;
    if (gatherT) {
        int rem = m & 4095;
        int l = rem >> 4;
        int t = rem & 15;
        srcRow = (b * TT + t) * LLEN + l;
    }
    float4 v = ((const float4*)(X + (size_t)srcRow * DD))[tid];
    float ss = v.x * v.x + v.y * v.y + v.z * v.z + v.w * v.w;
    __shared__ float red[8];
#pragma unroll
    for (int o = 16; o > 0; o >>= 1) ss += __shfl_down_sync(0xffffffffu, ss, o);
    if ((tid & 31) == 0) red[tid >> 5] = ss;
    __syncthreads();
    float tot = red[0] + red[1] + red[2] + red[3] + red[4] + red[5] + red[6] + red[7];
    float r = rsqrtf(tot * (1.f / 1024.f) + 1e-6f);
    int d = tid * 4;
    const float* sh = mods + (b * 9 + shIdx) * DD;
    const float* sc = mods + (b * 9 + scIdx) * DD;
    float o0 = v.x * r * w[d + 0] * (1.f + sc[d + 0]) + sh[d + 0];
    float o1 = v.y * r * w[d + 1] * (1.f + sc[d + 1]) + sh[d + 1];
    float o2 = v.z * r * w[d + 2] * (1.f + sc[d + 2]) + sh[d + 2];
    float o3 = v.w * r * w[d + 3] * (1.f + sc[d + 3]) + sh[d + 3];
    __nv_bfloat162* row = (__nv_bfloat162*)(XN + (size_t)m * DD);
    row[2 * tid]     = __floats2bfloat162_rn(o0, o1);
    row[2 * tid + 1] = __floats2bfloat162_rn(o2, o3);
}

// ---------------- attention: fused qk-rmsnorm + RoPE, plain-exp softmax ----------------
// QKV arrives bf16; converted to fp32 during staging. Hot loop stays fp32 f32x2.
template <int SEQ, int BH>
__global__ __launch_bounds__(256, 1) void attn_kernel(const __nv_bfloat16* __restrict__ QKV,
                                                      __nv_bfloat16* __restrict__ ATT,
                                                      const float* __restrict__ qw,
                                                      const float* __restrict__ kw,
                                                      const float* __restrict__ ct,
                                                      const float* __restrict__ st) {
    extern __shared__ float4 sm4[];
    float4* ks = sm4;                      // [BH][SEQ][16]
    float4* vs = sm4 + BH * SEQ * 16;
    int tid = threadIdx.x;
    int unit0 = blockIdx.x * BH;

    for (int i = tid; i < BH * SEQ * 16; i += 256) {
        int u = i / (SEQ * 16);
        int rem = i % (SEQ * 16);
        int j = rem / 16, d4 = rem % 16;
        int bh = unit0 + u;
        int batch = bh >> 4, head = bh & 15;
        const __nv_bfloat16* base = QKV + (size_t)(batch * SEQ + j) * QKVN + head * HDIM;
        const uint2* kp = (const uint2*)(base + DD);
        const uint2* vp = (const uint2*)(base + 2 * DD);
        ks[i] = bf4_to_f4(kp[d4]);
        vs[i] = bf4_to_f4(vp[d4]);
    }
    __syncthreads();

    // ---- K rows: rmsnorm(kw) + rope, in SMEM (1 row per thread) ----
    {
        float4* kr = ks + tid * 16;
        int posk = tid % SEQ;
        float4 kv[16];
        float s = 0.f;
#pragma unroll
        for (int i = 0; i < 16; i++) {
            kv[i] = kr[i];
            s += kv[i].x * kv[i].x + kv[i].y * kv[i].y + kv[i].z * kv[i].z + kv[i].w * kv[i].w;
        }
        float r = rsqrtf(s * (1.f / 64.f) + 1e-6f);
        const float4* w4 = (const float4*)kw;
        const float4* c4 = (const float4*)(ct + posk * 64);
        const float4* s4 = (const float4*)(st + posk * 64);
        float4 kn[16];
#pragma unroll
        for (int i = 0; i < 16; i++) {
            float4 ww = w4[i];
            kn[i] = make_float4(kv[i].x * r * ww.x, kv[i].y * r * ww.y,
                                kv[i].z * r * ww.z, kv[i].w * r * ww.w);
        }
#pragma unroll
        for (int i = 0; i < 8; i++) {
            float4 ca = c4[i], sa = s4[i], cb = c4[i + 8], sb = s4[i + 8];
            float4 lo = kn[i], hi = kn[i + 8];
            kr[i]     = make_float4(lo.x * ca.x - hi.x * sa.x, lo.y * ca.y - hi.y * sa.y,
                                    lo.z * ca.z - hi.z * sa.z, lo.w * ca.w - hi.w * sa.w);
            kr[i + 8] = make_float4(hi.x * cb.x + lo.x * sb.x, hi.y * cb.y + lo.y * sb.y,
                                    hi.z * cb.z + lo.z * sb.z, hi.w * cb.w + lo.w * sb.w);
        }
    }
    __syncthreads();

    int u = tid / SEQ, qi = tid % SEQ;
    int bh = unit0 + u;
    int batch = bh >> 4, head = bh & 15;
    const uint2* qp = (const uint2*)(QKV + (size_t)(batch * SEQ + qi) * QKVN + head * HDIM);
    u64t q2[32];
    {
        float4 q[16];
        float s = 0.f;
#pragma unroll
        for (int i = 0; i < 16; i++) {
            q[i] = bf4_to_f4(qp[i]);
            s += q[i].x * q[i].x + q[i].y * q[i].y + q[i].z * q[i].z + q[i].w * q[i].w;
        }
        float r = rsqrtf(s * (1.f / 64.f) + 1e-6f);
        const float4* w4 = (const float4*)qw;
        const float4* c4 = (const float4*)(ct + qi * 64);
        const float4* s4 = (const float4*)(st + qi * 64);
        float4 qn[16];
#pragma unroll
        for (int i = 0; i < 16; i++) {
            float4 ww = w4[i];
            qn[i] = make_float4(q[i].x * r * ww.x, q[i].y * r * ww.y,
                                q[i].z * r * ww.z, q[i].w * r * ww.w);
        }
#pragma unroll
        for (int i = 0; i < 8; i++) {
            float4 ca = c4[i], sa = s4[i], cb = c4[i + 8], sb = s4[i + 8];
            float4 lo = qn[i], hi = qn[i + 8];
            float4 e0 = make_float4(lo.x * ca.x - hi.x * sa.x, lo.y * ca.y - hi.y * sa.y,
                                    lo.z * ca.z - hi.z * sa.z, lo.w * ca.w - hi.w * sa.w);
            float4 e1 = make_float4(hi.x * cb.x + lo.x * sb.x, hi.y * cb.y + lo.y * sb.y,
                                    hi.z * cb.z + lo.z * sb.z, hi.w * cb.w + lo.w * sb.w);
            q2[2 * i]          = pk2(e0.x, e0.y);
            q2[2 * i + 1]      = pk2(e0.z, e0.w);
            q2[2 * (i + 8)]     = pk2(e1.x, e1.y);
            q2[2 * (i + 8) + 1] = pk2(e1.z, e1.w);
        }
    }

    const u64t z2 = pk2(0.f, 0.f);
    u64t o2[32];
#pragma unroll
    for (int i = 0; i < 32; i++) o2[i] = z2;

    float lsum = 0.f;
    const double2* kr2 = (const double2*)(ks + u * SEQ * 16);   // 16B vectors
    const double2* vr2 = (const double2*)(vs + u * SEQ * 16);
    for (int j = 0; j < SEQ; j++) {
        const double2* kj = kr2 + j * 16;
        u64t a0 = z2, a1 = z2, a2 = z2, a3 = z2;
#pragma unroll
        for (int i = 0; i < 8; i++) {
            double2 t0 = kj[2 * i];
            double2 t1 = kj[2 * i + 1];
            a0 = fma2_(q2[4 * i + 0], (u64t)__double_as_longlong(t0.x), a0);
            a1 = fma2_(q2[4 * i + 1], (u64t)__double_as_longlong(t0.y), a1);
            a2 = fma2_(q2[4 * i + 2], (u64t)__double_as_longlong(t1.x), a2);
            a3 = fma2_(q2[4 * i + 3], (u64t)__double_as_longlong(t1.y), a3);
        }
        float2 f0 = upk2(a0), f1 = upk2(a1), f2 = upk2(a2), f3 = upk2(a3);
        float s = ((f0.x + f0.y) + (f1.x + f1.y)) + ((f2.x + f2.y) + (f3.x + f3.y));
        float p = __expf(s * 0.125f);
        lsum += p;
        u64t p2 = pk2(p, p);
        const double2* vj = vr2 + j * 16;
#pragma unroll
        for (int i = 0; i < 16; i++) {
            double2 t = vj[i];
            o2[2 * i]     = fma2_(p2, (u64t)__double_as_longlong(t.x), o2[2 * i]);
            o2[2 * i + 1] = fma2_(p2, (u64t)__double_as_longlong(t.y), o2[2 * i + 1]);
        }
    }
    float inv = 1.f / lsum;
    __nv_bfloat162* op = (__nv_bfloat162*)(ATT + (size_t)(batch * SEQ + qi) * DD + head * HDIM);
#pragma unroll
    for (int i = 0; i < 32; i++) {
        float2 f = upk2(o2[i]);
        op[i] = __floats2bfloat162_rn(f.x * inv, f.y * inv);
    }
}

// ---------------- bf16 tensor-core GEMM (ldmatrix, K=32 x 3-stage ring, 2 CTA/SM) ----------------
// C = A(MxK) * B(NxK)^T + epilogue.  Requires M % 128 == 0, N % 128 == 0, K % 32 == 0
// (all call sites satisfy this: N in {3072, 1024, 5504}).
// One barrier per K-tile (top-of-loop sync also orders reads before slot reuse).
// EPI 1: C[m,n] = resid[m,n] + gate[b,n]*(acc+bias)     (N==1024)
// EPI 2: like 1, scattered through (B,L,T)->(B,T,L)      (N==1024)
// EPI 3: fused SiLU-GLU: pairs (2j,2j+1)=(h1,h2) -> bf16 H[m,j], row stride HFFP
// EPI 4: bf16 output with bias (QKV)
#define BG_STG 10240           // 128 rows * 80 bytes (32 bf16 data + 8 pad)
#define BG_B_OFF (3 * BG_STG)  // 30720
#define BG_SMEM (6 * BG_STG)   // 61440

template <int EPI>
__global__ __launch_bounds__(128, 2) void bgemm(const __nv_bfloat16* __restrict__ A,
                                                const __nv_bfloat16* __restrict__ Bw,
                                                const float* __restrict__ bias,
                                                float* __restrict__ C,
                                                const float* __restrict__ resid,
                                                const float* __restrict__ gate,
                                                int M, int N, int K) {
    extern __shared__ char smem[];
    const int tid = threadIdx.x;
    const int wid = tid >> 5, lane = tid & 31;
    const int g = lane >> 2, t = lane & 3;
    const int wm0 = (wid >> 1) * 64, wn0 = (wid & 1) * 64;
    const int m0 = blockIdx.y * 128, n0 = blockIdx.x * 128;

    const __nv_bfloat16* aRow = A + (size_t)(m0 + tid) * K;
    const __nv_bfloat16* bRow = Bw + (size_t)(n0 + tid) * K;
    const uint32_t smemBase = (uint32_t)__cvta_generic_to_shared(smem);
    const uint32_t aBase = smemBase + tid * 80;
    const uint32_t bBase = aBase + BG_B_OFF;

    // ldmatrix per-thread fragment addresses (within a stage)
    const uint32_t aFrag = smemBase + (wm0 + (lane & 15)) * 80 + (lane >> 4) * 16;
    const uint32_t bFrag = smemBase + BG_B_OFF
                         + (wn0 + (lane & 7) + ((lane >> 4) & 1) * 8) * 80
                         + ((lane >> 3) & 1) * 16;

    float acc[4][8][4];
#pragma unroll
    for (int i = 0; i < 4; i++)
#pragma unroll
        for (int j = 0; j < 8; j++)
#pragma unroll
            for (int r = 0; r < 4; r++) acc[i][j][r] = 0.f;

    const int ntiles = K >> 5;

    // prologue: prefetch tiles 0,1
#pragma unroll
    for (int p = 0; p < 2; p++) {
        int kt = p * 32;
#pragma unroll
        for (int q = 0; q < 4; q++) cp16(aBase + p * BG_STG + q * 16, aRow + kt + q * 8);
#pragma unroll
        for (int q = 0; q < 4; q++) cp16(bBase + p * BG_STG + q * 16, bRow + kt + q * 8);
        cp_commit();
    }

    for (int tt = 0; tt < ntiles; tt++) {
        cp_wait1();
        __syncthreads();

        // prefetch tile tt+2 into slot (tt+2)%3
        if (tt + 2 < ntiles) {
            int slot = (tt + 2) % 3;
            int kt = (tt + 2) * 32;
#pragma unroll
            for (int q = 0; q < 4; q++) cp16(aBase + slot * BG_STG + q * 16, aRow + kt + q * 8);
#pragma unroll
            for (int q = 0; q < 4; q++) cp16(bBase + slot * BG_STG + q * 16, bRow + kt + q * 8);
        }
        cp_commit();

        // compute from slot tt%3 via ldmatrix
        const uint32_t aS = aFrag + (tt % 3) * BG_STG;
        const uint32_t bS = bFrag + (tt % 3) * BG_STG;
#pragma unroll
        for (int ks = 0; ks < 2; ks++) {
            uint32_t a[4][4], b[8][2];
#pragma unroll
            for (int i = 0; i < 4; i++)
                LDSM4(a[i][0], a[i][1], a[i][2], a[i][3], aS + i * (16 * 80) + ks * 32);
#pragma unroll
            for (int jj = 0; jj < 4; jj++)
                LDSM4(b[2 * jj][0], b[2 * jj][1], b[2 * jj + 1][0], b[2 * jj + 1][1],
                      bS + jj * (16 * 80) + ks * 32);
#pragma unroll
            for (int i = 0; i < 4; i++)
#pragma unroll
                for (int j = 0; j < 8; j++) {
                    asm volatile(
                        "mma.sync.aligned.m16n8k16.row.col.f32.bf16.bf16.f32 "
                        "{%0,%1,%2,%3},{%4,%5,%6,%7},{%8,%9},{%0,%1,%2,%3};\n"
                        : "+f"(acc[i][j][0]), "+f"(acc[i][j][1]),
                          "+f"(acc[i][j][2]), "+f"(acc[i][j][3])
                        : "r"(a[i][0]), "r"(a[i][1]), "r"(a[i][2]), "r"(a[i][3]),
                          "r"(b[j][0]), "r"(b[j][1]));
                }
        }
        // no trailing __syncthreads(): next iteration's top sync provides the ordering
    }

    // epilogue.  batch index is constant per tile (4096 % 128 == 0).
    const int bb = m0 >> 12;
#pragma unroll
    for (int j = 0; j < 8; j++) {
        const int nc = n0 + wn0 + 8 * j + 2 * t;
        const float b0 = bias[nc], b1 = bias[nc + 1];
        float g0, g1;
        if (EPI == 1 || EPI == 2) {
            g0 = gate[bb * MODN + nc];
            g1 = gate[bb * MODN + nc + 1];
        }
#pragma unroll
        for (int i = 0; i < 4; i++) {
            int mr = m0 + wm0 + 16 * i + g;
#pragma unroll
            for (int h = 0; h < 2; h++) {
                int m = mr + h * 8;
                float v0 = acc[i][j][2 * h + 0] + b0;
                float v1 = acc[i][j][2 * h + 1] + b1;
                if (EPI == 1) {
                    size_t idx = (size_t)m * N + nc;
                    float2 rr = *(const float2*)(resid + idx);
                    *(float2*)(C + idx) = make_float2(rr.x + g0 * v0, rr.y + g1 * v1);
                } else if (EPI == 2) {
                    int rem = m & 4095;
                    int l = rem >> 4;
                    int ti = rem & 15;
                    size_t idx = ((size_t)((bb * TT + ti) * LLEN + l)) * N + nc;
                    float2 rr = *(const float2*)(resid + idx);
                    *(float2*)(C + idx) = make_float2(rr.x + g0 * v0, rr.y + g1 * v1);
                } else if (EPI == 3) {  // fused SiLU-GLU, interleaved pairs -> bf16 H
                    int pj = nc >> 1;
                    float hh = 0.f;
                    if (pj < HFF) {
                        float e = __expf(-v0);
                        hh = __fdividef(v0, 1.f + e) * v1;
                    }
                    ((__nv_bfloat16*)C)[(size_t)m * HFFP + pj] = __float2bfloat16(hh);
                } else {  // EPI == 4: bf16 output with bias (QKV)
                    ((__nv_bfloat162*)C)[((size_t)m * N + nc) >> 1] = __floats2bfloat162_rn(v0, v1);
                }
            }
        }
    }
}

// ---------------- host orchestration ----------------
extern "C" void kernel_launch(void* const* d_in, const int* in_sizes, int n_in,
                              void* d_out, int out_size) {
    const float* x       = (const float*)d_in[0];
    const float* c       = (const float*)d_in[1];
    const float* cos_s   = (const float*)d_in[2];
    const float* sin_s   = (const float*)d_in[3];
    const float* cos_t   = (const float*)d_in[4];
    const float* sin_t   = (const float*)d_in[5];
    const float* norm1_w = (const float*)d_in[6];
    const float* norm2_w = (const float*)d_in[7];
    const float* norm3_w = (const float*)d_in[8];
    const float* qkv_s_w = (const float*)d_in[9];
    const float* qkv_s_b = (const float*)d_in[10];
    const float* qn_s_w  = (const float*)d_in[11];
    const float* kn_s_w  = (const float*)d_in[12];
    const float* proj_s_w= (const float*)d_in[13];
    const float* proj_s_b= (const float*)d_in[14];
    const float* qkv_t_w = (const float*)d_in[15];
    const float* qkv_t_b = (const float*)d_in[16];
    const float* qn_t_w  = (const float*)d_in[17];
    const float* kn_t_w  = (const float*)d_in[18];
    const float* proj_t_w= (const float*)d_in[19];
    const float* proj_t_b= (const float*)d_in[20];
    const float* w12_w   = (const float*)d_in[21];
    const float* w12_b   = (const float*)d_in[22];
    const float* w3_w    = (const float*)d_in[23];
    const float* w3_b    = (const float*)d_in[24];
    const float* ada_w   = (const float*)d_in[25];
    const float* ada_b   = (const float*)d_in[26];
    float* out = (float*)d_out;

    float *X, *MODS, *SC, *W12B;
    __nv_bfloat16 *QKV, *XN, *ATT, *H, *W3P, *WQS, *WPS, *WQT, *WPT, *W12I;
    cudaGetSymbolAddress((void**)&X,   g_X);
    cudaGetSymbolAddress((void**)&MODS,g_MODS);
    cudaGetSymbolAddress((void**)&SC,  g_SC);
    cudaGetSymbolAddress((void**)&W12B,g_W12B);
    cudaGetSymbolAddress((void**)&QKV, g_QKV);
    cudaGetSymbolAddress((void**)&XN,  g_XN);
    cudaGetSymbolAddress((void**)&ATT, g_ATT);
    cudaGetSymbolAddress((void**)&H,   g_H);
    cudaGetSymbolAddress((void**)&W3P, g_W3P);
    cudaGetSymbolAddress((void**)&WQS, g_WQS);
    cudaGetSymbolAddress((void**)&WPS, g_WPS);
    cudaGetSymbolAddress((void**)&WQT, g_WQT);
    cudaGetSymbolAddress((void**)&WPT, g_WPT);
    cudaGetSymbolAddress((void**)&W12I,g_W12I);

    cudaFuncSetAttribute(attn_kernel<256, 1>, cudaFuncAttributeMaxDynamicSharedMemorySize, 131072);
    cudaFuncSetAttribute(attn_kernel<16, 16>, cudaFuncAttributeMaxDynamicSharedMemorySize, 131072);
    cudaFuncSetAttribute(bgemm<1>, cudaFuncAttributeMaxDynamicSharedMemorySize, BG_SMEM);
    cudaFuncSetAttribute(bgemm<2>, cudaFuncAttributeMaxDynamicSharedMemorySize, BG_SMEM);
    cudaFuncSetAttribute(bgemm<3>, cudaFuncAttributeMaxDynamicSharedMemorySize, BG_SMEM);
    cudaFuncSetAttribute(bgemm<4>, cudaFuncAttributeMaxDynamicSharedMemorySize, BG_SMEM);

    // init + weight conversion to bf16
    siluc_kernel<<<(BSZ * DD + 255) / 256, 256>>>(c, SC);
    mods_kernel<<<BSZ * MODN / 8, 256>>>(SC, ada_w, ada_b, MODS);
    tobf16_kernel<<<QKVN * DD / 4 / 256, 256>>>((const float4*)qkv_s_w, (__nv_bfloat162*)WQS, QKVN * DD / 4);
    tobf16_kernel<<<DD * DD / 4 / 256, 256>>>((const float4*)proj_s_w, (__nv_bfloat162*)WPS, DD * DD / 4);
    tobf16_kernel<<<QKVN * DD / 4 / 256, 256>>>((const float4*)qkv_t_w, (__nv_bfloat162*)WQT, QKVN * DD / 4);
    tobf16_kernel<<<DD * DD / 4 / 256, 256>>>((const float4*)proj_t_w, (__nv_bfloat162*)WPT, DD * DD / 4);
    w12prep_kernel<<<(W12P * DD / 2 + 255) / 256, 256>>>(w12_w, w12_b, (__nv_bfloat162*)W12I, W12B);
    padw3_kernel<<<(DD * HFFP / 2 + 255) / 256, 256>>>(w3_w, (__nv_bfloat162*)W3P);

    dim3 gq(QKVN / 128, MTOK / 128);
    dim3 gp(DD / 128, MTOK / 128);
    dim3 g12(W12P / 128, MTOK / 128);

    // ---- spatial attention branch (residual read straight from input x) ----
    rmsnorm_mod_kernel<<<MTOK, 256>>>(x, XN, norm1_w, MODS, 0, 1, 0);
    bgemm<4><<<gq, 128, BG_SMEM>>>(XN, WQS, qkv_s_b, (float*)QKV, nullptr, nullptr, MTOK, QKVN, DD);
    attn_kernel<256, 1><<<BSZ * TT * NHEADS, 256, 131072>>>(QKV, ATT, qn_s_w, kn_s_w, cos_s, sin_s);
    bgemm<1><<<gp, 128, BG_SMEM>>>(ATT, WPS, proj_s_b, X, x, MODS + 2 * DD, MTOK, DD, DD);

    // ---- temporal attention branch ----
    rmsnorm_mod_kernel<<<MTOK, 256>>>(X, XN, norm2_w, MODS, 3, 4, 1);
    bgemm<4><<<gq, 128, BG_SMEM>>>(XN, WQT, qkv_t_b, (float*)QKV, nullptr, nullptr, MTOK, QKVN, DD);
    attn_kernel<16, 16><<<BSZ * LLEN * NHEADS / 16, 256, 131072>>>(QKV, ATT, qn_t_w, kn_t_w, cos_t, sin_t);
    bgemm<2><<<gp, 128, BG_SMEM>>>(ATT, WPT, proj_t_b, X, X, MODS + 5 * DD, MTOK, DD, DD);

    // ---- MLP (SiLU-GLU fused into w12 GEMM epilogue) ----
    rmsnorm_mod_kernel<<<MTOK, 256>>>(X, XN, norm3_w, MODS, 6, 7, 0);
    bgemm<3><<<g12, 128, BG_SMEM>>>(XN, W12I, W12B, (float*)H, nullptr, nullptr, MTOK, W12P, DD);
    bgemm<1><<<gp, 128, BG_SMEM>>>(H, W3P, w3_b, out, X, MODS + 8 * DD, MTOK, DD, HFFP);
}

// round 15
// speedup vs baseline: 1.0829x; 1.0196x over previous
#include <cuda_runtime.h>
#include <cuda_bf16.h>
#include <cstdint>
#include <math.h>

// ---------------- problem constants ----------------
#define DD    1024
#define NHEADS 16
#define HDIM  64
#define BSZ   2
#define TT    16
#define LLEN  256
#define MTOK  8192          // B*T*L
#define HFF   2730
#define HFFP  2752          // padded (= 43*64)
#define W12P  5504          // 2*HFFP interleaved output width
#define QKVN  3072
#define MODN  9216          // 9*D

// ---------------- device scratch (allocation-free rule) ----------------
__device__ float g_X  [(size_t)MTOK * DD];
__device__ float g_MODS[BSZ * MODN];
__device__ float g_SC  [BSZ * DD];
__device__ float g_W12B[W12P];
// bf16 buffers
__device__ __nv_bfloat16 g_QKV[(size_t)MTOK * QKVN];
__device__ __nv_bfloat16 g_XN [(size_t)MTOK * DD];
__device__ __nv_bfloat16 g_ATT[(size_t)MTOK * DD];
__device__ __nv_bfloat16 g_H  [(size_t)MTOK * HFFP];
__device__ __nv_bfloat16 g_W3P[(size_t)DD * HFFP];
__device__ __nv_bfloat16 g_WQS[(size_t)QKVN * DD];
__device__ __nv_bfloat16 g_WPS[(size_t)DD * DD];
__device__ __nv_bfloat16 g_WQT[(size_t)QKVN * DD];
__device__ __nv_bfloat16 g_WPT[(size_t)DD * DD];
__device__ __nv_bfloat16 g_W12I[(size_t)W12P * DD];

// ---------------- PTX helpers ----------------
__device__ __forceinline__ void cp16(uint32_t s, const void* g) {
    asm volatile("cp.async.cg.shared.global [%0], [%1], 16;\n" :: "r"(s), "l"(g));
}
__device__ __forceinline__ void cp_commit() { asm volatile("cp.async.commit_group;\n"); }
__device__ __forceinline__ void cp_wait1()  { asm volatile("cp.async.wait_group 1;\n"); }

#define LDSM4(r0, r1, r2, r3, addr) \
    asm volatile("ldmatrix.sync.aligned.m8n8.x4.shared.b16 {%0,%1,%2,%3}, [%4];" \
        : "=r"(r0), "=r"(r1), "=r"(r2), "=r"(r3) : "r"(addr))

typedef unsigned long long u64t;
__device__ __forceinline__ u64t pk2(float lo, float hi) {
    u64t r; asm("mov.b64 %0, {%1,%2};" : "=l"(r) : "f"(lo), "f"(hi)); return r;
}
__device__ __forceinline__ u64t fma2_(u64t a, u64t b, u64t c) {
    u64t d; asm("fma.rn.f32x2 %0,%1,%2,%3;" : "=l"(d) : "l"(a), "l"(b), "l"(c)); return d;
}
__device__ __forceinline__ float2 upk2(u64t v) {
    float2 f; asm("mov.b64 {%0,%1}, %2;" : "=f"(f.x), "=f"(f.y) : "l"(v)); return f;
}
// 4 consecutive bf16 (as uint2) -> float4
__device__ __forceinline__ float4 bf4_to_f4(uint2 u) {
    __nv_bfloat162 a = *reinterpret_cast<__nv_bfloat162*>(&u.x);
    __nv_bfloat162 b = *reinterpret_cast<__nv_bfloat162*>(&u.y);
    float2 fa = __bfloat1622float2(a);
    float2 fb = __bfloat1622float2(b);
    return make_float4(fa.x, fa.y, fb.x, fb.y);
}

// ---------------- merged weight-prep kernel (single launch) ----------------
// Regions (flat unit index):
//  [0,R0)      WQS  float4 -> 2x bf162        (QKVN*DD/4)
//  [R0,R1)     WPS  float4 -> 2x bf162        (DD*DD/4)
//  [R1,R2)     WQT                            (QKVN*DD/4)
//  [R2,R3)     WPT                            (DD*DD/4)
//  [R3,R4)     W12I interleave + BI           (W12P*DD/2 bf162 units)
//  [R4,R5)     W3P  pad                       (DD*HFFP/2 bf162 units)
#define WPREP_R0 (QKVN * DD / 4)
#define WPREP_R1 (WPREP_R0 + DD * DD / 4)
#define WPREP_R2 (WPREP_R1 + QKVN * DD / 4)
#define WPREP_R3 (WPREP_R2 + DD * DD / 4)
#define WPREP_R4 (WPREP_R3 + W12P * (DD / 2))
#define WPREP_R5 (WPREP_R4 + DD * (HFFP / 2))

__device__ __forceinline__ void cvt4(const float4* src, __nv_bfloat162* dst, int i) {
    float4 v = src[i];
    dst[2 * i]     = __floats2bfloat162_rn(v.x, v.y);
    dst[2 * i + 1] = __floats2bfloat162_rn(v.z, v.w);
}

__global__ void wprep_kernel(const float4* __restrict__ qs, const float4* __restrict__ ps,
                             const float4* __restrict__ qt, const float4* __restrict__ pt,
                             const float* __restrict__ w12w, const float* __restrict__ w12b,
                             const float* __restrict__ w3,
                             __nv_bfloat162* __restrict__ WQS, __nv_bfloat162* __restrict__ WPS,
                             __nv_bfloat162* __restrict__ WQT, __nv_bfloat162* __restrict__ WPT,
                             __nv_bfloat162* __restrict__ W12I, float* __restrict__ BI,
                             __nv_bfloat162* __restrict__ W3P) {
    int idx = blockIdx.x * 256 + threadIdx.x;
    if (idx < WPREP_R0) {
        cvt4(qs, WQS, idx);
    } else if (idx < WPREP_R1) {
        cvt4(ps, WPS, idx - WPREP_R0);
    } else if (idx < WPREP_R2) {
        cvt4(qt, WQT, idx - WPREP_R1);
    } else if (idx < WPREP_R3) {
        cvt4(pt, WPT, idx - WPREP_R2);
    } else if (idx < WPREP_R4) {
        int u = idx - WPREP_R3;                 // over W12P * DD/2
        int n = u / (DD / 2);
        int k = (u % (DD / 2)) * 2;
        int j = n >> 1, s = n & 1;
        float a = 0.f, b = 0.f;
        if (j < HFF) {
            const float* src = w12w + (size_t)(j + s * HFF) * DD + k;
            a = src[0]; b = src[1];
        }
        W12I[u] = __floats2bfloat162_rn(a, b);
        if (k == 0) BI[n] = (j < HFF) ? w12b[j + s * HFF] : 0.f;
    } else if (idx < WPREP_R5) {
        int u = idx - WPREP_R4;                 // over DD * HFFP/2
        int n = u / (HFFP / 2), kp = u % (HFFP / 2);
        int k = kp * 2;
        float a = (k < HFF) ? w3[(size_t)n * HFF + k] : 0.f;
        float b = (k < HFF) ? w3[(size_t)n * HFF + k + 1] : 0.f;
        W3P[u] = __floats2bfloat162_rn(a, b);
    }
}

// ---------------- small utility kernels ----------------
__global__ void siluc_kernel(const float* __restrict__ c, float* __restrict__ out) {
    int i = blockIdx.x * 256 + threadIdx.x;
    if (i < BSZ * DD) {
        float v = c[i];
        out[i] = v / (1.f + expf(-v));
    }
}

// mods = silu(c) @ ada_w.T + ada_b   -> (B, 9*D)   (tiny, fp32 exact)
__global__ void mods_kernel(const float* __restrict__ sc, const float* __restrict__ aw,
                            const float* __restrict__ ab, float* __restrict__ mods) {
    int gw = (blockIdx.x * blockDim.x + threadIdx.x) >> 5;
    int lane = threadIdx.x & 31;
    if (gw >= BSZ * MODN) return;
    int b = gw / MODN, n = gw % MODN;
    const float4* cv = (const float4*)(sc + b * DD);
    const float4* wv = (const float4*)(aw + (size_t)n * DD);
    float s = 0.f;
#pragma unroll
    for (int k = 0; k < 8; k++) {
        float4 a = cv[lane + k * 32];
        float4 w = wv[lane + k * 32];
        s += a.x * w.x + a.y * w.y + a.z * w.z + a.w * w.w;
    }
#pragma unroll
    for (int o = 16; o > 0; o >>= 1) s += __shfl_down_sync(0xffffffffu, s, o);
    if (lane == 0) mods[gw] = s + ab[n];
}

// rmsnorm + adaLN modulation -> bf16
__global__ void rmsnorm_mod_kernel(const float* __restrict__ X, __nv_bfloat16* __restrict__ XN,
                                   const float* __restrict__ w, const float* __restrict__ mods,
                                   int shIdx, int scIdx, int gatherT) {
    int m = blockIdx.x;
    int tid = threadIdx.x;
    int b = m >> 12;
    int srcRow = m;
    if (gatherT) {
        int rem = m & 4095;
        int l = rem >> 4;
        int t = rem & 15;
        srcRow = (b * TT + t) * LLEN + l;
    }
    float4 v = ((const float4*)(X + (size_t)srcRow * DD))[tid];
    float ss = v.x * v.x + v.y * v.y + v.z * v.z + v.w * v.w;
    __shared__ float red[8];
#pragma unroll
    for (int o = 16; o > 0; o >>= 1) ss += __shfl_down_sync(0xffffffffu, ss, o);
    if ((tid & 31) == 0) red[tid >> 5] = ss;
    __syncthreads();
    float tot = red[0] + red[1] + red[2] + red[3] + red[4] + red[5] + red[6] + red[7];
    float r = rsqrtf(tot * (1.f / 1024.f) + 1e-6f);
    int d = tid * 4;
    const float* sh = mods + (b * 9 + shIdx) * DD;
    const float* sc = mods + (b * 9 + scIdx) * DD;
    float o0 = v.x * r * w[d + 0] * (1.f + sc[d + 0]) + sh[d + 0];
    float o1 = v.y * r * w[d + 1] * (1.f + sc[d + 1]) + sh[d + 1];
    float o2 = v.z * r * w[d + 2] * (1.f + sc[d + 2]) + sh[d + 2];
    float o3 = v.w * r * w[d + 3] * (1.f + sc[d + 3]) + sh[d + 3];
    __nv_bfloat162* row = (__nv_bfloat162*)(XN + (size_t)m * DD);
    row[2 * tid]     = __floats2bfloat162_rn(o0, o1);
    row[2 * tid + 1] = __floats2bfloat162_rn(o2, o3);
}

// ---------------- attention: fused qk-rmsnorm + RoPE, plain-exp softmax ----------------
// QKV arrives bf16; converted to fp32 during staging. Hot loop stays fp32 f32x2.
template <int SEQ, int BH>
__global__ __launch_bounds__(256, 1) void attn_kernel(const __nv_bfloat16* __restrict__ QKV,
                                                      __nv_bfloat16* __restrict__ ATT,
                                                      const float* __restrict__ qw,
                                                      const float* __restrict__ kw,
                                                      const float* __restrict__ ct,
                                                      const float* __restrict__ st) {
    extern __shared__ float4 sm4[];
    float4* ks = sm4;                      // [BH][SEQ][16]
    float4* vs = sm4 + BH * SEQ * 16;
    int tid = threadIdx.x;
    int unit0 = blockIdx.x * BH;

    for (int i = tid; i < BH * SEQ * 16; i += 256) {
        int u = i / (SEQ * 16);
        int rem = i % (SEQ * 16);
        int j = rem / 16, d4 = rem % 16;
        int bh = unit0 + u;
        int batch = bh >> 4, head = bh & 15;
        const __nv_bfloat16* base = QKV + (size_t)(batch * SEQ + j) * QKVN + head * HDIM;
        const uint2* kp = (const uint2*)(base + DD);
        const uint2* vp = (const uint2*)(base + 2 * DD);
        ks[i] = bf4_to_f4(kp[d4]);
        vs[i] = bf4_to_f4(vp[d4]);
    }
    __syncthreads();

    // ---- K rows: rmsnorm(kw) + rope, in SMEM (1 row per thread) ----
    {
        float4* kr = ks + tid * 16;
        int posk = tid % SEQ;
        float4 kv[16];
        float s = 0.f;
#pragma unroll
        for (int i = 0; i < 16; i++) {
            kv[i] = kr[i];
            s += kv[i].x * kv[i].x + kv[i].y * kv[i].y + kv[i].z * kv[i].z + kv[i].w * kv[i].w;
        }
        float r = rsqrtf(s * (1.f / 64.f) + 1e-6f);
        const float4* w4 = (const float4*)kw;
        const float4* c4 = (const float4*)(ct + posk * 64);
        const float4* s4 = (const float4*)(st + posk * 64);
        float4 kn[16];
#pragma unroll
        for (int i = 0; i < 16; i++) {
            float4 ww = w4[i];
            kn[i] = make_float4(kv[i].x * r * ww.x, kv[i].y * r * ww.y,
                                kv[i].z * r * ww.z, kv[i].w * r * ww.w);
        }
#pragma unroll
        for (int i = 0; i < 8; i++) {
            float4 ca = c4[i], sa = s4[i], cb = c4[i + 8], sb = s4[i + 8];
            float4 lo = kn[i], hi = kn[i + 8];
            kr[i]     = make_float4(lo.x * ca.x - hi.x * sa.x, lo.y * ca.y - hi.y * sa.y,
                                    lo.z * ca.z - hi.z * sa.z, lo.w * ca.w - hi.w * sa.w);
            kr[i + 8] = make_float4(hi.x * cb.x + lo.x * sb.x, hi.y * cb.y + lo.y * sb.y,
                                    hi.z * cb.z + lo.z * sb.z, hi.w * cb.w + lo.w * sb.w);
        }
    }
    __syncthreads();

    int u = tid / SEQ, qi = tid % SEQ;
    int bh = unit0 + u;
    int batch = bh >> 4, head = bh & 15;
    const uint2* qp = (const uint2*)(QKV + (size_t)(batch * SEQ + qi) * QKVN + head * HDIM);
    u64t q2[32];
    {
        float4 q[16];
        float s = 0.f;
#pragma unroll
        for (int i = 0; i < 16; i++) {
            q[i] = bf4_to_f4(qp[i]);
            s += q[i].x * q[i].x + q[i].y * q[i].y + q[i].z * q[i].z + q[i].w * q[i].w;
        }
        float r = rsqrtf(s * (1.f / 64.f) + 1e-6f);
        const float4* w4 = (const float4*)qw;
        const float4* c4 = (const float4*)(ct + qi * 64);
        const float4* s4 = (const float4*)(st + qi * 64);
        float4 qn[16];
#pragma unroll
        for (int i = 0; i < 16; i++) {
            float4 ww = w4[i];
            qn[i] = make_float4(q[i].x * r * ww.x, q[i].y * r * ww.y,
                                q[i].z * r * ww.z, q[i].w * r * ww.w);
        }
#pragma unroll
        for (int i = 0; i < 8; i++) {
            float4 ca = c4[i], sa = s4[i], cb = c4[i + 8], sb = s4[i + 8];
            float4 lo = qn[i], hi = qn[i + 8];
            float4 e0 = make_float4(lo.x * ca.x - hi.x * sa.x, lo.y * ca.y - hi.y * sa.y,
                                    lo.z * ca.z - hi.z * sa.z, lo.w * ca.w - hi.w * sa.w);
            float4 e1 = make_float4(hi.x * cb.x + lo.x * sb.x, hi.y * cb.y + lo.y * sb.y,
                                    hi.z * cb.z + lo.z * sb.z, hi.w * cb.w + lo.w * sb.w);
            q2[2 * i]          = pk2(e0.x, e0.y);
            q2[2 * i + 1]      = pk2(e0.z, e0.w);
            q2[2 * (i + 8)]     = pk2(e1.x, e1.y);
            q2[2 * (i + 8) + 1] = pk2(e1.z, e1.w);
        }
    }

    const u64t z2 = pk2(0.f, 0.f);
    u64t o2[32];
#pragma unroll
    for (int i = 0; i < 32; i++) o2[i] = z2;

    float lsum = 0.f;
    const double2* kr2 = (const double2*)(ks + u * SEQ * 16);   // 16B vectors
    const double2* vr2 = (const double2*)(vs + u * SEQ * 16);
    for (int j = 0; j < SEQ; j++) {
        const double2* kj = kr2 + j * 16;
        u64t a0 = z2, a1 = z2, a2 = z2, a3 = z2;
#pragma unroll
        for (int i = 0; i < 8; i++) {
            double2 t0 = kj[2 * i];
            double2 t1 = kj[2 * i + 1];
            a0 = fma2_(q2[4 * i + 0], (u64t)__double_as_longlong(t0.x), a0);
            a1 = fma2_(q2[4 * i + 1], (u64t)__double_as_longlong(t0.y), a1);
            a2 = fma2_(q2[4 * i + 2], (u64t)__double_as_longlong(t1.x), a2);
            a3 = fma2_(q2[4 * i + 3], (u64t)__double_as_longlong(t1.y), a3);
        }
        float2 f0 = upk2(a0), f1 = upk2(a1), f2 = upk2(a2), f3 = upk2(a3);
        float s = ((f0.x + f0.y) + (f1.x + f1.y)) + ((f2.x + f2.y) + (f3.x + f3.y));
        float p = __expf(s * 0.125f);
        lsum += p;
        u64t p2 = pk2(p, p);
        const double2* vj = vr2 + j * 16;
#pragma unroll
        for (int i = 0; i < 16; i++) {
            double2 t = vj[i];
            o2[2 * i]     = fma2_(p2, (u64t)__double_as_longlong(t.x), o2[2 * i]);
            o2[2 * i + 1] = fma2_(p2, (u64t)__double_as_longlong(t.y), o2[2 * i + 1]);
        }
    }
    float inv = 1.f / lsum;
    __nv_bfloat162* op = (__nv_bfloat162*)(ATT + (size_t)(batch * SEQ + qi) * DD + head * HDIM);
#pragma unroll
    for (int i = 0; i < 32; i++) {
        float2 f = upk2(o2[i]);
        op[i] = __floats2bfloat162_rn(f.x * inv, f.y * inv);
    }
}

// ---------------- bf16 tensor-core GEMM (ldmatrix, K=32 x 3-stage ring, 2 CTA/SM) ----------------
// C = A(MxK) * B(NxK)^T + epilogue.  Requires M % 128 == 0, N % 128 == 0, K % 32 == 0.
// One barrier per K-tile (top-of-loop sync also orders reads before slot reuse).
// EPI 1: C[m,n] = resid[m,n] + gate[b,n]*(acc+bias)     (N==1024)
// EPI 2: like 1, scattered through (B,L,T)->(B,T,L)      (N==1024)
// EPI 3: fused SiLU-GLU: pairs (2j,2j+1)=(h1,h2) -> bf16 H[m,j], row stride HFFP
// EPI 4: bf16 output with bias (QKV)
#define BG_STG 10240           // 128 rows * 80 bytes (32 bf16 data + 8 pad)
#define BG_B_OFF (3 * BG_STG)  // 30720
#define BG_SMEM (6 * BG_STG)   // 61440

template <int EPI>
__global__ __launch_bounds__(128, 2) void bgemm(const __nv_bfloat16* __restrict__ A,
                                                const __nv_bfloat16* __restrict__ Bw,
                                                const float* __restrict__ bias,
                                                float* __restrict__ C,
                                                const float* __restrict__ resid,
                                                const float* __restrict__ gate,
                                                int M, int N, int K) {
    extern __shared__ char smem[];
    const int tid = threadIdx.x;
    const int wid = tid >> 5, lane = tid & 31;
    const int g = lane >> 2, t = lane & 3;
    const int wm0 = (wid >> 1) * 64, wn0 = (wid & 1) * 64;
    const int m0 = blockIdx.y * 128, n0 = blockIdx.x * 128;

    const __nv_bfloat16* aRow = A + (size_t)(m0 + tid) * K;
    const __nv_bfloat16* bRow = Bw + (size_t)(n0 + tid) * K;
    const uint32_t smemBase = (uint32_t)__cvta_generic_to_shared(smem);
    const uint32_t aBase = smemBase + tid * 80;
    const uint32_t bBase = aBase + BG_B_OFF;

    // ldmatrix per-thread fragment addresses (within a stage)
    const uint32_t aFrag = smemBase + (wm0 + (lane & 15)) * 80 + (lane >> 4) * 16;
    const uint32_t bFrag = smemBase + BG_B_OFF
                         + (wn0 + (lane & 7) + ((lane >> 4) & 1) * 8) * 80
                         + ((lane >> 3) & 1) * 16;

    float acc[4][8][4];
#pragma unroll
    for (int i = 0; i < 4; i++)
#pragma unroll
        for (int j = 0; j < 8; j++)
#pragma unroll
            for (int r = 0; r < 4; r++) acc[i][j][r] = 0.f;

    const int ntiles = K >> 5;

    // prologue: prefetch tiles 0,1
#pragma unroll
    for (int p = 0; p < 2; p++) {
        int kt = p * 32;
#pragma unroll
        for (int q = 0; q < 4; q++) cp16(aBase + p * BG_STG + q * 16, aRow + kt + q * 8);
#pragma unroll
        for (int q = 0; q < 4; q++) cp16(bBase + p * BG_STG + q * 16, bRow + kt + q * 8);
        cp_commit();
    }

    for (int tt = 0; tt < ntiles; tt++) {
        cp_wait1();
        __syncthreads();

        // prefetch tile tt+2 into slot (tt+2)%3
        if (tt + 2 < ntiles) {
            int slot = (tt + 2) % 3;
            int kt = (tt + 2) * 32;
#pragma unroll
            for (int q = 0; q < 4; q++) cp16(aBase + slot * BG_STG + q * 16, aRow + kt + q * 8);
#pragma unroll
            for (int q = 0; q < 4; q++) cp16(bBase + slot * BG_STG + q * 16, bRow + kt + q * 8);
        }
        cp_commit();

        // compute from slot tt%3 via ldmatrix
        const uint32_t aS = aFrag + (tt % 3) * BG_STG;
        const uint32_t bS = bFrag + (tt % 3) * BG_STG;
#pragma unroll
        for (int ks = 0; ks < 2; ks++) {
            uint32_t a[4][4], b[8][2];
#pragma unroll
            for (int i = 0; i < 4; i++)
                LDSM4(a[i][0], a[i][1], a[i][2], a[i][3], aS + i * (16 * 80) + ks * 32);
#pragma unroll
            for (int jj = 0; jj < 4; jj++)
                LDSM4(b[2 * jj][0], b[2 * jj][1], b[2 * jj + 1][0], b[2 * jj + 1][1],
                      bS + jj * (16 * 80) + ks * 32);
#pragma unroll
            for (int i = 0; i < 4; i++)
#pragma unroll
                for (int j = 0; j < 8; j++) {
                    asm volatile(
                        "mma.sync.aligned.m16n8k16.row.col.f32.bf16.bf16.f32 "
                        "{%0,%1,%2,%3},{%4,%5,%6,%7},{%8,%9},{%0,%1,%2,%3};\n"
                        : "+f"(acc[i][j][0]), "+f"(acc[i][j][1]),
                          "+f"(acc[i][j][2]), "+f"(acc[i][j][3])
                        : "r"(a[i][0]), "r"(a[i][1]), "r"(a[i][2]), "r"(a[i][3]),
                          "r"(b[j][0]), "r"(b[j][1]));
                }
        }
        // no trailing __syncthreads(): next iteration's top sync provides the ordering
    }

    // epilogue.  batch index is constant per tile (4096 % 128 == 0).
    const int bb = m0 >> 12;
#pragma unroll
    for (int j = 0; j < 8; j++) {
        const int nc = n0 + wn0 + 8 * j + 2 * t;
        const float b0 = bias[nc], b1 = bias[nc + 1];
        float g0, g1;
        if (EPI == 1 || EPI == 2) {
            g0 = gate[bb * MODN + nc];
            g1 = gate[bb * MODN + nc + 1];
        }
#pragma unroll
        for (int i = 0; i < 4; i++) {
            int mr = m0 + wm0 + 16 * i + g;
#pragma unroll
            for (int h = 0; h < 2; h++) {
                int m = mr + h * 8;
                float v0 = acc[i][j][2 * h + 0] + b0;
                float v1 = acc[i][j][2 * h + 1] + b1;
                if (EPI == 1) {
                    size_t idx = (size_t)m * N + nc;
                    float2 rr = *(const float2*)(resid + idx);
                    *(float2*)(C + idx) = make_float2(rr.x + g0 * v0, rr.y + g1 * v1);
                } else if (EPI == 2) {
                    int rem = m & 4095;
                    int l = rem >> 4;
                    int ti = rem & 15;
                    size_t idx = ((size_t)((bb * TT + ti) * LLEN + l)) * N + nc;
                    float2 rr = *(const float2*)(resid + idx);
                    *(float2*)(C + idx) = make_float2(rr.x + g0 * v0, rr.y + g1 * v1);
                } else if (EPI == 3) {  // fused SiLU-GLU, interleaved pairs -> bf16 H
                    int pj = nc >> 1;
                    float hh = 0.f;
                    if (pj < HFF) {
                        float e = __expf(-v0);
                        hh = __fdividef(v0, 1.f + e) * v1;
                    }
                    ((__nv_bfloat16*)C)[(size_t)m * HFFP + pj] = __float2bfloat16(hh);
                } else {  // EPI == 4: bf16 output with bias (QKV)
                    ((__nv_bfloat162*)C)[((size_t)m * N + nc) >> 1] = __floats2bfloat162_rn(v0, v1);
                }
            }
        }
    }
}

// ---------------- host orchestration ----------------
extern "C" void kernel_launch(void* const* d_in, const int* in_sizes, int n_in,
                              void* d_out, int out_size) {
    const float* x       = (const float*)d_in[0];
    const float* c       = (const float*)d_in[1];
    const float* cos_s   = (const float*)d_in[2];
    const float* sin_s   = (const float*)d_in[3];
    const float* cos_t   = (const float*)d_in[4];
    const float* sin_t   = (const float*)d_in[5];
    const float* norm1_w = (const float*)d_in[6];
    const float* norm2_w = (const float*)d_in[7];
    const float* norm3_w = (const float*)d_in[8];
    const float* qkv_s_w = (const float*)d_in[9];
    const float* qkv_s_b = (const float*)d_in[10];
    const float* qn_s_w  = (const float*)d_in[11];
    const float* kn_s_w  = (const float*)d_in[12];
    const float* proj_s_w= (const float*)d_in[13];
    const float* proj_s_b= (const float*)d_in[14];
    const float* qkv_t_w = (const float*)d_in[15];
    const float* qkv_t_b = (const float*)d_in[16];
    const float* qn_t_w  = (const float*)d_in[17];
    const float* kn_t_w  = (const float*)d_in[18];
    const float* proj_t_w= (const float*)d_in[19];
    const float* proj_t_b= (const float*)d_in[20];
    const float* w12_w   = (const float*)d_in[21];
    const float* w12_b   = (const float*)d_in[22];
    const float* w3_w    = (const float*)d_in[23];
    const float* w3_b    = (const float*)d_in[24];
    const float* ada_w   = (const float*)d_in[25];
    const float* ada_b   = (const float*)d_in[26];
    float* out = (float*)d_out;

    float *X, *MODS, *SC, *W12B;
    __nv_bfloat16 *QKV, *XN, *ATT, *H, *W3P, *WQS, *WPS, *WQT, *WPT, *W12I;
    cudaGetSymbolAddress((void**)&X,   g_X);
    cudaGetSymbolAddress((void**)&MODS,g_MODS);
    cudaGetSymbolAddress((void**)&SC,  g_SC);
    cudaGetSymbolAddress((void**)&W12B,g_W12B);
    cudaGetSymbolAddress((void**)&QKV, g_QKV);
    cudaGetSymbolAddress((void**)&XN,  g_XN);
    cudaGetSymbolAddress((void**)&ATT, g_ATT);
    cudaGetSymbolAddress((void**)&H,   g_H);
    cudaGetSymbolAddress((void**)&W3P, g_W3P);
    cudaGetSymbolAddress((void**)&WQS, g_WQS);
    cudaGetSymbolAddress((void**)&WPS, g_WPS);
    cudaGetSymbolAddress((void**)&WQT, g_WQT);
    cudaGetSymbolAddress((void**)&WPT, g_WPT);
    cudaGetSymbolAddress((void**)&W12I,g_W12I);

    cudaFuncSetAttribute(attn_kernel<256, 1>, cudaFuncAttributeMaxDynamicSharedMemorySize, 131072);
    cudaFuncSetAttribute(attn_kernel<16, 16>, cudaFuncAttributeMaxDynamicSharedMemorySize, 131072);
    cudaFuncSetAttribute(bgemm<1>, cudaFuncAttributeMaxDynamicSharedMemorySize, BG_SMEM);
    cudaFuncSetAttribute(bgemm<2>, cudaFuncAttributeMaxDynamicSharedMemorySize, BG_SMEM);
    cudaFuncSetAttribute(bgemm<3>, cudaFuncAttributeMaxDynamicSharedMemorySize, BG_SMEM);
    cudaFuncSetAttribute(bgemm<4>, cudaFuncAttributeMaxDynamicSharedMemorySize, BG_SMEM);

    // init + merged weight conversion (single launch)
    siluc_kernel<<<(BSZ * DD + 255) / 256, 256>>>(c, SC);
    mods_kernel<<<BSZ * MODN / 8, 256>>>(SC, ada_w, ada_b, MODS);
    wprep_kernel<<<(WPREP_R5 + 255) / 256, 256>>>(
        (const float4*)qkv_s_w, (const float4*)proj_s_w,
        (const float4*)qkv_t_w, (const float4*)proj_t_w,
        w12_w, w12_b, w3_w,
        (__nv_bfloat162*)WQS, (__nv_bfloat162*)WPS,
        (__nv_bfloat162*)WQT, (__nv_bfloat162*)WPT,
        (__nv_bfloat162*)W12I, W12B, (__nv_bfloat162*)W3P);

    dim3 gq(QKVN / 128, MTOK / 128);
    dim3 gp(DD / 128, MTOK / 128);
    dim3 g12(W12P / 128, MTOK / 128);

    // ---- spatial attention branch (residual read straight from input x) ----
    rmsnorm_mod_kernel<<<MTOK, 256>>>(x, XN, norm1_w, MODS, 0, 1, 0);
    bgemm<4><<<gq, 128, BG_SMEM>>>(XN, WQS, qkv_s_b, (float*)QKV, nullptr, nullptr, MTOK, QKVN, DD);
    attn_kernel<256, 1><<<BSZ * TT * NHEADS, 256, 131072>>>(QKV, ATT, qn_s_w, kn_s_w, cos_s, sin_s);
    bgemm<1><<<gp, 128, BG_SMEM>>>(ATT, WPS, proj_s_b, X, x, MODS + 2 * DD, MTOK, DD, DD);

    // ---- temporal attention branch ----
    rmsnorm_mod_kernel<<<MTOK, 256>>>(X, XN, norm2_w, MODS, 3, 4, 1);
    bgemm<4><<<gq, 128, BG_SMEM>>>(XN, WQT, qkv_t_b, (float*)QKV, nullptr, nullptr, MTOK, QKVN, DD);
    attn_kernel<16, 16><<<BSZ * LLEN * NHEADS / 16, 256, 131072>>>(QKV, ATT, qn_t_w, kn_t_w, cos_t, sin_t);
    bgemm<2><<<gp, 128, BG_SMEM>>>(ATT, WPT, proj_t_b, X, X, MODS + 5 * DD, MTOK, DD, DD);

    // ---- MLP (SiLU-GLU fused into w12 GEMM epilogue) ----
    rmsnorm_mod_kernel<<<MTOK, 256>>>(X, XN, norm3_w, MODS, 6, 7, 0);
    bgemm<3><<<g12, 128, BG_SMEM>>>(XN, W12I, W12B, (float*)H, nullptr, nullptr, MTOK, W12P, DD);
    bgemm<1><<<gp, 128, BG_SMEM>>>(H, W3P, w3_b, out, X, MODS + 8 * DD, MTOK, DD, HFFP);
}

// round 16
// speedup vs baseline: 1.0942x; 1.0105x over previous
#include <cuda_runtime.h>
#include <cuda_bf16.h>
#include <cstdint>
#include <math.h>

// ---------------- problem constants ----------------
#define DD    1024
#define NHEADS 16
#define HDIM  64
#define BSZ   2
#define TT    16
#define LLEN  256
#define MTOK  8192          // B*T*L
#define HFF   2730
#define HFFP  2752          // padded (= 43*64)
#define W12P  5504          // 2*HFFP interleaved output width
#define QKVN  3072
#define MODN  9216          // 9*D

// ---------------- device scratch (allocation-free rule) ----------------
__device__ float g_X  [(size_t)MTOK * DD];
__device__ float g_MODS[BSZ * MODN];
__device__ float g_SC  [BSZ * DD];
__device__ float g_W12B[W12P];
// bf16 buffers
__device__ __nv_bfloat16 g_QKV[(size_t)MTOK * QKVN];
__device__ __nv_bfloat16 g_XN [(size_t)MTOK * DD];
__device__ __nv_bfloat16 g_ATT[(size_t)MTOK * DD];
__device__ __nv_bfloat16 g_H  [(size_t)MTOK * HFFP];
__device__ __nv_bfloat16 g_W3P[(size_t)DD * HFFP];
__device__ __nv_bfloat16 g_WQS[(size_t)QKVN * DD];
__device__ __nv_bfloat16 g_WPS[(size_t)DD * DD];
__device__ __nv_bfloat16 g_WQT[(size_t)QKVN * DD];
__device__ __nv_bfloat16 g_WPT[(size_t)DD * DD];
__device__ __nv_bfloat16 g_W12I[(size_t)W12P * DD];

// ---------------- PTX helpers ----------------
__device__ __forceinline__ void cp16(uint32_t s, const void* g) {
    asm volatile("cp.async.cg.shared.global [%0], [%1], 16;\n" :: "r"(s), "l"(g));
}
__device__ __forceinline__ void cp_commit() { asm volatile("cp.async.commit_group;\n"); }
__device__ __forceinline__ void cp_wait1()  { asm volatile("cp.async.wait_group 1;\n"); }

#define LDSM4(r0, r1, r2, r3, addr) \
    asm volatile("ldmatrix.sync.aligned.m8n8.x4.shared.b16 {%0,%1,%2,%3}, [%4];" \
        : "=r"(r0), "=r"(r1), "=r"(r2), "=r"(r3) : "r"(addr))

typedef unsigned long long u64t;
__device__ __forceinline__ u64t pk2(float lo, float hi) {
    u64t r; asm("mov.b64 %0, {%1,%2};" : "=l"(r) : "f"(lo), "f"(hi)); return r;
}
__device__ __forceinline__ u64t fma2_(u64t a, u64t b, u64t c) {
    u64t d; asm("fma.rn.f32x2 %0,%1,%2,%3;" : "=l"(d) : "l"(a), "l"(b), "l"(c)); return d;
}
__device__ __forceinline__ float2 upk2(u64t v) {
    float2 f; asm("mov.b64 {%0,%1}, %2;" : "=f"(f.x), "=f"(f.y) : "l"(v)); return f;
}
// 4 consecutive bf16 (as uint2) -> float4
__device__ __forceinline__ float4 bf4_to_f4(uint2 u) {
    __nv_bfloat162 a = *reinterpret_cast<__nv_bfloat162*>(&u.x);
    __nv_bfloat162 b = *reinterpret_cast<__nv_bfloat162*>(&u.y);
    float2 fa = __bfloat1622float2(a);
    float2 fb = __bfloat1622float2(b);
    return make_float4(fa.x, fa.y, fb.x, fb.y);
}

// ---------------- merged weight-prep kernel (single launch) ----------------
#define WPREP_R0 (QKVN * DD / 4)
#define WPREP_R1 (WPREP_R0 + DD * DD / 4)
#define WPREP_R2 (WPREP_R1 + QKVN * DD / 4)
#define WPREP_R3 (WPREP_R2 + DD * DD / 4)
#define WPREP_R4 (WPREP_R3 + W12P * (DD / 2))
#define WPREP_R5 (WPREP_R4 + DD * (HFFP / 2))

__device__ __forceinline__ void cvt4(const float4* src, __nv_bfloat162* dst, int i) {
    float4 v = src[i];
    dst[2 * i]     = __floats2bfloat162_rn(v.x, v.y);
    dst[2 * i + 1] = __floats2bfloat162_rn(v.z, v.w);
}

__global__ void wprep_kernel(const float4* __restrict__ qs, const float4* __restrict__ ps,
                             const float4* __restrict__ qt, const float4* __restrict__ pt,
                             const float* __restrict__ w12w, const float* __restrict__ w12b,
                             const float* __restrict__ w3,
                             __nv_bfloat162* __restrict__ WQS, __nv_bfloat162* __restrict__ WPS,
                             __nv_bfloat162* __restrict__ WQT, __nv_bfloat162* __restrict__ WPT,
                             __nv_bfloat162* __restrict__ W12I, float* __restrict__ BI,
                             __nv_bfloat162* __restrict__ W3P) {
    int idx = blockIdx.x * 256 + threadIdx.x;
    if (idx < WPREP_R0) {
        cvt4(qs, WQS, idx);
    } else if (idx < WPREP_R1) {
        cvt4(ps, WPS, idx - WPREP_R0);
    } else if (idx < WPREP_R2) {
        cvt4(qt, WQT, idx - WPREP_R1);
    } else if (idx < WPREP_R3) {
        cvt4(pt, WPT, idx - WPREP_R2);
    } else if (idx < WPREP_R4) {
        int u = idx - WPREP_R3;                 // over W12P * DD/2
        int n = u / (DD / 2);
        int k = (u % (DD / 2)) * 2;
        int j = n >> 1, s = n & 1;
        float a = 0.f, b = 0.f;
        if (j < HFF) {
            const float* src = w12w + (size_t)(j + s * HFF) * DD + k;
            a = src[0]; b = src[1];
        }
        W12I[u] = __floats2bfloat162_rn(a, b);
        if (k == 0) BI[n] = (j < HFF) ? w12b[j + s * HFF] : 0.f;
    } else if (idx < WPREP_R5) {
        int u = idx - WPREP_R4;                 // over DD * HFFP/2
        int n = u / (HFFP / 2), kp = u % (HFFP / 2);
        int k = kp * 2;
        float a = (k < HFF) ? w3[(size_t)n * HFF + k] : 0.f;
        float b = (k < HFF) ? w3[(size_t)n * HFF + k + 1] : 0.f;
        W3P[u] = __floats2bfloat162_rn(a, b);
    }
}

// ---------------- small utility kernels ----------------
__global__ void siluc_kernel(const float* __restrict__ c, float* __restrict__ out) {
    int i = blockIdx.x * 256 + threadIdx.x;
    if (i < BSZ * DD) {
        float v = c[i];
        out[i] = v / (1.f + expf(-v));
    }
}

// mods = silu(c) @ ada_w.T + ada_b   -> (B, 9*D)   (tiny, fp32 exact)
__global__ void mods_kernel(const float* __restrict__ sc, const float* __restrict__ aw,
                            const float* __restrict__ ab, float* __restrict__ mods) {
    int gw = (blockIdx.x * blockDim.x + threadIdx.x) >> 5;
    int lane = threadIdx.x & 31;
    if (gw >= BSZ * MODN) return;
    int b = gw / MODN, n = gw % MODN;
    const float4* cv = (const float4*)(sc + b * DD);
    const float4* wv = (const float4*)(aw + (size_t)n * DD);
    float s = 0.f;
#pragma unroll
    for (int k = 0; k < 8; k++) {
        float4 a = cv[lane + k * 32];
        float4 w = wv[lane + k * 32];
        s += a.x * w.x + a.y * w.y + a.z * w.z + a.w * w.w;
    }
#pragma unroll
    for (int o = 16; o > 0; o >>= 1) s += __shfl_down_sync(0xffffffffu, s, o);
    if (lane == 0) mods[gw] = s + ab[n];
}

// rmsnorm + adaLN modulation -> bf16 (all operand loads vectorized float4)
__global__ void rmsnorm_mod_kernel(const float* __restrict__ X, __nv_bfloat16* __restrict__ XN,
                                   const float* __restrict__ w, const float* __restrict__ mods,
                                   int shIdx, int scIdx, int gatherT) {
    int m = blockIdx.x;
    int tid = threadIdx.x;
    int b = m >> 12;
    int srcRow = m;
    if (gatherT) {
        int rem = m & 4095;
        int l = rem >> 4;
        int t = rem & 15;
        srcRow = (b * TT + t) * LLEN + l;
    }
    float4 v = ((const float4*)(X + (size_t)srcRow * DD))[tid];
    float ss = v.x * v.x + v.y * v.y + v.z * v.z + v.w * v.w;
    __shared__ float red[8];
#pragma unroll
    for (int o = 16; o > 0; o >>= 1) ss += __shfl_down_sync(0xffffffffu, ss, o);
    if ((tid & 31) == 0) red[tid >> 5] = ss;
    __syncthreads();
    float tot = red[0] + red[1] + red[2] + red[3] + red[4] + red[5] + red[6] + red[7];
    float r = rsqrtf(tot * (1.f / 1024.f) + 1e-6f);
    float4 w4  = ((const float4*)w)[tid];
    float4 sh4 = ((const float4*)(mods + (b * 9 + shIdx) * DD))[tid];
    float4 sc4 = ((const float4*)(mods + (b * 9 + scIdx) * DD))[tid];
    float o0 = v.x * r * w4.x * (1.f + sc4.x) + sh4.x;
    float o1 = v.y * r * w4.y * (1.f + sc4.y) + sh4.y;
    float o2 = v.z * r * w4.z * (1.f + sc4.z) + sh4.z;
    float o3 = v.w * r * w4.w * (1.f + sc4.w) + sh4.w;
    __nv_bfloat162* row = (__nv_bfloat162*)(XN + (size_t)m * DD);
    row[2 * tid]     = __floats2bfloat162_rn(o0, o1);
    row[2 * tid + 1] = __floats2bfloat162_rn(o2, o3);
}

// ---------------- attention: fused qk-rmsnorm + RoPE, plain-exp softmax ----------------
// QKV arrives bf16; converted to fp32 during staging. Hot loop stays fp32 f32x2.
template <int SEQ, int BH>
__global__ __launch_bounds__(256, 1) void attn_kernel(const __nv_bfloat16* __restrict__ QKV,
                                                      __nv_bfloat16* __restrict__ ATT,
                                                      const float* __restrict__ qw,
                                                      const float* __restrict__ kw,
                                                      const float* __restrict__ ct,
                                                      const float* __restrict__ st) {
    extern __shared__ float4 sm4[];
    float4* ks = sm4;                      // [BH][SEQ][16]
    float4* vs = sm4 + BH * SEQ * 16;
    int tid = threadIdx.x;
    int unit0 = blockIdx.x * BH;

    for (int i = tid; i < BH * SEQ * 16; i += 256) {
        int u = i / (SEQ * 16);
        int rem = i % (SEQ * 16);
        int j = rem / 16, d4 = rem % 16;
        int bh = unit0 + u;
        int batch = bh >> 4, head = bh & 15;
        const __nv_bfloat16* base = QKV + (size_t)(batch * SEQ + j) * QKVN + head * HDIM;
        const uint2* kp = (const uint2*)(base + DD);
        const uint2* vp = (const uint2*)(base + 2 * DD);
        ks[i] = bf4_to_f4(kp[d4]);
        vs[i] = bf4_to_f4(vp[d4]);
    }
    __syncthreads();

    // ---- K rows: rmsnorm(kw) + rope, in SMEM (1 row per thread) ----
    {
        float4* kr = ks + tid * 16;
        int posk = tid % SEQ;
        float4 kv[16];
        float s = 0.f;
#pragma unroll
        for (int i = 0; i < 16; i++) {
            kv[i] = kr[i];
            s += kv[i].x * kv[i].x + kv[i].y * kv[i].y + kv[i].z * kv[i].z + kv[i].w * kv[i].w;
        }
        float r = rsqrtf(s * (1.f / 64.f) + 1e-6f);
        const float4* w4 = (const float4*)kw;
        const float4* c4 = (const float4*)(ct + posk * 64);
        const float4* s4 = (const float4*)(st + posk * 64);
        float4 kn[16];
#pragma unroll
        for (int i = 0; i < 16; i++) {
            float4 ww = w4[i];
            kn[i] = make_float4(kv[i].x * r * ww.x, kv[i].y * r * ww.y,
                                kv[i].z * r * ww.z, kv[i].w * r * ww.w);
        }
#pragma unroll
        for (int i = 0; i < 8; i++) {
            float4 ca = c4[i], sa = s4[i], cb = c4[i + 8], sb = s4[i + 8];
            float4 lo = kn[i], hi = kn[i + 8];
            kr[i]     = make_float4(lo.x * ca.x - hi.x * sa.x, lo.y * ca.y - hi.y * sa.y,
                                    lo.z * ca.z - hi.z * sa.z, lo.w * ca.w - hi.w * sa.w);
            kr[i + 8] = make_float4(hi.x * cb.x + lo.x * sb.x, hi.y * cb.y + lo.y * sb.y,
                                    hi.z * cb.z + lo.z * sb.z, hi.w * cb.w + lo.w * sb.w);
        }
    }
    __syncthreads();

    int u = tid / SEQ, qi = tid % SEQ;
    int bh = unit0 + u;
    int batch = bh >> 4, head = bh & 15;
    const uint2* qp = (const uint2*)(QKV + (size_t)(batch * SEQ + qi) * QKVN + head * HDIM);
    u64t q2[32];
    {
        float4 q[16];
        float s = 0.f;
#pragma unroll
        for (int i = 0; i < 16; i++) {
            q[i] = bf4_to_f4(qp[i]);
            s += q[i].x * q[i].x + q[i].y * q[i].y + q[i].z * q[i].z + q[i].w * q[i].w;
        }
        float r = rsqrtf(s * (1.f / 64.f) + 1e-6f);
        const float4* w4 = (const float4*)qw;
        const float4* c4 = (const float4*)(ct + qi * 64);
        const float4* s4 = (const float4*)(st + qi * 64);
        float4 qn[16];
#pragma unroll
        for (int i = 0; i < 16; i++) {
            float4 ww = w4[i];
            qn[i] = make_float4(q[i].x * r * ww.x, q[i].y * r * ww.y,
                                q[i].z * r * ww.z, q[i].w * r * ww.w);
        }
#pragma unroll
        for (int i = 0; i < 8; i++) {
            float4 ca = c4[i], sa = s4[i], cb = c4[i + 8], sb = s4[i + 8];
            float4 lo = qn[i], hi = qn[i + 8];
            float4 e0 = make_float4(lo.x * ca.x - hi.x * sa.x, lo.y * ca.y - hi.y * sa.y,
                                    lo.z * ca.z - hi.z * sa.z, lo.w * ca.w - hi.w * sa.w);
            float4 e1 = make_float4(hi.x * cb.x + lo.x * sb.x, hi.y * cb.y + lo.y * sb.y,
                                    hi.z * cb.z + lo.z * sb.z, hi.w * cb.w + lo.w * sb.w);
            q2[2 * i]          = pk2(e0.x, e0.y);
            q2[2 * i + 1]      = pk2(e0.z, e0.w);
            q2[2 * (i + 8)]     = pk2(e1.x, e1.y);
            q2[2 * (i + 8) + 1] = pk2(e1.z, e1.w);
        }
    }

    const u64t z2 = pk2(0.f, 0.f);
    u64t o2[32];
#pragma unroll
    for (int i = 0; i < 32; i++) o2[i] = z2;

    float lsum = 0.f;
    const double2* kr2 = (const double2*)(ks + u * SEQ * 16);   // 16B vectors
    const double2* vr2 = (const double2*)(vs + u * SEQ * 16);
    for (int j = 0; j < SEQ; j++) {
        const double2* kj = kr2 + j * 16;
        u64t a0 = z2, a1 = z2, a2 = z2, a3 = z2;
#pragma unroll
        for (int i = 0; i < 8; i++) {
            double2 t0 = kj[2 * i];
            double2 t1 = kj[2 * i + 1];
            a0 = fma2_(q2[4 * i + 0], (u64t)__double_as_longlong(t0.x), a0);
            a1 = fma2_(q2[4 * i + 1], (u64t)__double_as_longlong(t0.y), a1);
            a2 = fma2_(q2[4 * i + 2], (u64t)__double_as_longlong(t1.x), a2);
            a3 = fma2_(q2[4 * i + 3], (u64t)__double_as_longlong(t1.y), a3);
        }
        float2 f0 = upk2(a0), f1 = upk2(a1), f2 = upk2(a2), f3 = upk2(a3);
        float s = ((f0.x + f0.y) + (f1.x + f1.y)) + ((f2.x + f2.y) + (f3.x + f3.y));
        float p = __expf(s * 0.125f);
        lsum += p;
        u64t p2 = pk2(p, p);
        const double2* vj = vr2 + j * 16;
#pragma unroll
        for (int i = 0; i < 16; i++) {
            double2 t = vj[i];
            o2[2 * i]     = fma2_(p2, (u64t)__double_as_longlong(t.x), o2[2 * i]);
            o2[2 * i + 1] = fma2_(p2, (u64t)__double_as_longlong(t.y), o2[2 * i + 1]);
        }
    }
    float inv = 1.f / lsum;
    __nv_bfloat162* op = (__nv_bfloat162*)(ATT + (size_t)(batch * SEQ + qi) * DD + head * HDIM);
#pragma unroll
    for (int i = 0; i < 32; i++) {
        float2 f = upk2(o2[i]);
        op[i] = __floats2bfloat162_rn(f.x * inv, f.y * inv);
    }
}

// ---------------- bf16 tensor-core GEMM (ldmatrix, K=32 x 3-stage ring, 2 CTA/SM) ----------------
// C = A(MxK) * B(NxK)^T + epilogue.  Requires M % 128 == 0, N % 128 == 0, K % 32 == 0.
// EPI 1: C[m,n] = resid[m,n] + gate[b,n]*(acc+bias)     (N==1024)
// EPI 2: like 1, scattered through (B,L,T)->(B,T,L)      (N==1024)
// EPI 3: fused SiLU-GLU: pairs (2j,2j+1)=(h1,h2) -> bf16 H[m,j], row stride HFFP
// EPI 4: bf16 output with bias (QKV)
#define BG_STG 10240           // 128 rows * 80 bytes (32 bf16 data + 8 pad)
#define BG_B_OFF (3 * BG_STG)  // 30720
#define BG_SMEM (6 * BG_STG)   // 61440

template <int EPI>
__global__ __launch_bounds__(128, 2) void bgemm(const __nv_bfloat16* __restrict__ A,
                                                const __nv_bfloat16* __restrict__ Bw,
                                                const float* __restrict__ bias,
                                                float* __restrict__ C,
                                                const float* __restrict__ resid,
                                                const float* __restrict__ gate,
                                                int M, int N, int K) {
    extern __shared__ char smem[];
    const int tid = threadIdx.x;
    const int wid = tid >> 5, lane = tid & 31;
    const int g = lane >> 2, t = lane & 3;
    const int wm0 = (wid >> 1) * 64, wn0 = (wid & 1) * 64;
    const int m0 = blockIdx.y * 128, n0 = blockIdx.x * 128;

    const __nv_bfloat16* aRow = A + (size_t)(m0 + tid) * K;
    const __nv_bfloat16* bRow = Bw + (size_t)(n0 + tid) * K;
    const uint32_t smemBase = (uint32_t)__cvta_generic_to_shared(smem);
    const uint32_t aBase = smemBase + tid * 80;
    const uint32_t bBase = aBase + BG_B_OFF;

    // ldmatrix per-thread fragment addresses (within a stage)
    const uint32_t aFrag = smemBase + (wm0 + (lane & 15)) * 80 + (lane >> 4) * 16;
    const uint32_t bFrag = smemBase + BG_B_OFF
                         + (wn0 + (lane & 7) + ((lane >> 4) & 1) * 8) * 80
                         + ((lane >> 3) & 1) * 16;

    float acc[4][8][4];
#pragma unroll
    for (int i = 0; i < 4; i++)
#pragma unroll
        for (int j = 0; j < 8; j++)
#pragma unroll
            for (int r = 0; r < 4; r++) acc[i][j][r] = 0.f;

    const int ntiles = K >> 5;

    // prologue: prefetch tiles 0,1
#pragma unroll
    for (int p = 0; p < 2; p++) {
        int kt = p * 32;
#pragma unroll
        for (int q = 0; q < 4; q++) cp16(aBase + p * BG_STG + q * 16, aRow + kt + q * 8);
#pragma unroll
        for (int q = 0; q < 4; q++) cp16(bBase + p * BG_STG + q * 16, bRow + kt + q * 8);
        cp_commit();
    }

    for (int tt = 0; tt < ntiles; tt++) {
        cp_wait1();
        __syncthreads();

        // prefetch tile tt+2 into slot (tt+2)%3
        if (tt + 2 < ntiles) {
            int slot = (tt + 2) % 3;
            int kt = (tt + 2) * 32;
#pragma unroll
            for (int q = 0; q < 4; q++) cp16(aBase + slot * BG_STG + q * 16, aRow + kt + q * 8);
#pragma unroll
            for (int q = 0; q < 4; q++) cp16(bBase + slot * BG_STG + q * 16, bRow + kt + q * 8);
        }
        cp_commit();

        // compute from slot tt%3 via ldmatrix
        const uint32_t aS = aFrag + (tt % 3) * BG_STG;
        const uint32_t bS = bFrag + (tt % 3) * BG_STG;
#pragma unroll
        for (int ks = 0; ks < 2; ks++) {
            uint32_t a[4][4], b[8][2];
#pragma unroll
            for (int i = 0; i < 4; i++)
                LDSM4(a[i][0], a[i][1], a[i][2], a[i][3], aS + i * (16 * 80) + ks * 32);
#pragma unroll
            for (int jj = 0; jj < 4; jj++)
                LDSM4(b[2 * jj][0], b[2 * jj][1], b[2 * jj + 1][0], b[2 * jj + 1][1],
                      bS + jj * (16 * 80) + ks * 32);
#pragma unroll
            for (int i = 0; i < 4; i++)
#pragma unroll
                for (int j = 0; j < 8; j++) {
                    asm volatile(
                        "mma.sync.aligned.m16n8k16.row.col.f32.bf16.bf16.f32 "
                        "{%0,%1,%2,%3},{%4,%5,%6,%7},{%8,%9},{%0,%1,%2,%3};\n"
                        : "+f"(acc[i][j][0]), "+f"(acc[i][j][1]),
                          "+f"(acc[i][j][2]), "+f"(acc[i][j][3])
                        : "r"(a[i][0]), "r"(a[i][1]), "r"(a[i][2]), "r"(a[i][3]),
                          "r"(b[j][0]), "r"(b[j][1]));
                }
        }
        // no trailing __syncthreads(): next iteration's top sync provides the ordering
    }

    // epilogue.  batch index is constant per tile (4096 % 128 == 0).
    const int bb = m0 >> 12;
#pragma unroll
    for (int j = 0; j < 8; j++) {
        const int nc = n0 + wn0 + 8 * j + 2 * t;
        const float b0 = bias[nc], b1 = bias[nc + 1];
        float g0, g1;
        if (EPI == 1 || EPI == 2) {
            g0 = gate[bb * MODN + nc];
            g1 = gate[bb * MODN + nc + 1];
        }
#pragma unroll
        for (int i = 0; i < 4; i++) {
            int mr = m0 + wm0 + 16 * i + g;
#pragma unroll
            for (int h = 0; h < 2; h++) {
                int m = mr + h * 8;
                float v0 = acc[i][j][2 * h + 0] + b0;
                float v1 = acc[i][j][2 * h + 1] + b1;
                if (EPI == 1) {
                    size_t idx = (size_t)m * N + nc;
                    float2 rr = *(const float2*)(resid + idx);
                    *(float2*)(C + idx) = make_float2(rr.x + g0 * v0, rr.y + g1 * v1);
                } else if (EPI == 2) {
                    int rem = m & 4095;
                    int l = rem >> 4;
                    int ti = rem & 15;
                    size_t idx = ((size_t)((bb * TT + ti) * LLEN + l)) * N + nc;
                    float2 rr = *(const float2*)(resid + idx);
                    *(float2*)(C + idx) = make_float2(rr.x + g0 * v0, rr.y + g1 * v1);
                } else if (EPI == 3) {  // fused SiLU-GLU, interleaved pairs -> bf16 H
                    int pj = nc >> 1;
                    float hh = 0.f;
                    if (pj < HFF) {
                        float e = __expf(-v0);
                        hh = __fdividef(v0, 1.f + e) * v1;
                    }
                    ((__nv_bfloat16*)C)[(size_t)m * HFFP + pj] = __float2bfloat16(hh);
                } else {  // EPI == 4: bf16 output with bias (QKV)
                    ((__nv_bfloat162*)C)[((size_t)m * N + nc) >> 1] = __floats2bfloat162_rn(v0, v1);
                }
            }
        }
    }
}

// ---------------- host orchestration ----------------
extern "C" void kernel_launch(void* const* d_in, const int* in_sizes, int n_in,
                              void* d_out, int out_size) {
    const float* x       = (const float*)d_in[0];
    const float* c       = (const float*)d_in[1];
    const float* cos_s   = (const float*)d_in[2];
    const float* sin_s   = (const float*)d_in[3];
    const float* cos_t   = (const float*)d_in[4];
    const float* sin_t   = (const float*)d_in[5];
    const float* norm1_w = (const float*)d_in[6];
    const float* norm2_w = (const float*)d_in[7];
    const float* norm3_w = (const float*)d_in[8];
    const float* qkv_s_w = (const float*)d_in[9];
    const float* qkv_s_b = (const float*)d_in[10];
    const float* qn_s_w  = (const float*)d_in[11];
    const float* kn_s_w  = (const float*)d_in[12];
    const float* proj_s_w= (const float*)d_in[13];
    const float* proj_s_b= (const float*)d_in[14];
    const float* qkv_t_w = (const float*)d_in[15];
    const float* qkv_t_b = (const float*)d_in[16];
    const float* qn_t_w  = (const float*)d_in[17];
    const float* kn_t_w  = (const float*)d_in[18];
    const float* proj_t_w= (const float*)d_in[19];
    const float* proj_t_b= (const float*)d_in[20];
    const float* w12_w   = (const float*)d_in[21];
    const float* w12_b   = (const float*)d_in[22];
    const float* w3_w    = (const float*)d_in[23];
    const float* w3_b    = (const float*)d_in[24];
    const float* ada_w   = (const float*)d_in[25];
    const float* ada_b   = (const float*)d_in[26];
    float* out = (float*)d_out;

    float *X, *MODS, *SC, *W12B;
    __nv_bfloat16 *QKV, *XN, *ATT, *H, *W3P, *WQS, *WPS, *WQT, *WPT, *W12I;
    cudaGetSymbolAddress((void**)&X,   g_X);
    cudaGetSymbolAddress((void**)&MODS,g_MODS);
    cudaGetSymbolAddress((void**)&SC,  g_SC);
    cudaGetSymbolAddress((void**)&W12B,g_W12B);
    cudaGetSymbolAddress((void**)&QKV, g_QKV);
    cudaGetSymbolAddress((void**)&XN,  g_XN);
    cudaGetSymbolAddress((void**)&ATT, g_ATT);
    cudaGetSymbolAddress((void**)&H,   g_H);
    cudaGetSymbolAddress((void**)&W3P, g_W3P);
    cudaGetSymbolAddress((void**)&WQS, g_WQS);
    cudaGetSymbolAddress((void**)&WPS, g_WPS);
    cudaGetSymbolAddress((void**)&WQT, g_WQT);
    cudaGetSymbolAddress((void**)&WPT, g_WPT);
    cudaGetSymbolAddress((void**)&W12I,g_W12I);

    cudaFuncSetAttribute(attn_kernel<256, 1>, cudaFuncAttributeMaxDynamicSharedMemorySize, 131072);
    cudaFuncSetAttribute(attn_kernel<16, 16>, cudaFuncAttributeMaxDynamicSharedMemorySize, 131072);
    cudaFuncSetAttribute(bgemm<1>, cudaFuncAttributeMaxDynamicSharedMemorySize, BG_SMEM);
    cudaFuncSetAttribute(bgemm<2>, cudaFuncAttributeMaxDynamicSharedMemorySize, BG_SMEM);
    cudaFuncSetAttribute(bgemm<3>, cudaFuncAttributeMaxDynamicSharedMemorySize, BG_SMEM);
    cudaFuncSetAttribute(bgemm<4>, cudaFuncAttributeMaxDynamicSharedMemorySize, BG_SMEM);

    // init + merged weight conversion (single launch)
    siluc_kernel<<<(BSZ * DD + 255) / 256, 256>>>(c, SC);
    mods_kernel<<<BSZ * MODN / 8, 256>>>(SC, ada_w, ada_b, MODS);
    wprep_kernel<<<(WPREP_R5 + 255) / 256, 256>>>(
        (const float4*)qkv_s_w, (const float4*)proj_s_w,
        (const float4*)qkv_t_w, (const float4*)proj_t_w,
        w12_w, w12_b, w3_w,
        (__nv_bfloat162*)WQS, (__nv_bfloat162*)WPS,
        (__nv_bfloat162*)WQT, (__nv_bfloat162*)WPT,
        (__nv_bfloat162*)W12I, W12B, (__nv_bfloat162*)W3P);

    dim3 gq(QKVN / 128, MTOK / 128);
    dim3 gp(DD / 128, MTOK / 128);
    dim3 g12(W12P / 128, MTOK / 128);

    // ---- spatial attention branch (residual read straight from input x) ----
    rmsnorm_mod_kernel<<<MTOK, 256>>>(x, XN, norm1_w, MODS, 0, 1, 0);
    bgemm<4><<<gq, 128, BG_SMEM>>>(XN, WQS, qkv_s_b, (float*)QKV, nullptr, nullptr, MTOK, QKVN, DD);
    attn_kernel<256, 1><<<BSZ * TT * NHEADS, 256, 131072>>>(QKV, ATT, qn_s_w, kn_s_w, cos_s, sin_s);
    bgemm<1><<<gp, 128, BG_SMEM>>>(ATT, WPS, proj_s_b, X, x, MODS + 2 * DD, MTOK, DD, DD);

    // ---- temporal attention branch ----
    rmsnorm_mod_kernel<<<MTOK, 256>>>(X, XN, norm2_w, MODS, 3, 4, 1);
    bgemm<4><<<gq, 128, BG_SMEM>>>(XN, WQT, qkv_t_b, (float*)QKV, nullptr, nullptr, MTOK, QKVN, DD);
    attn_kernel<16, 16><<<BSZ * LLEN * NHEADS / 16, 256, 131072>>>(QKV, ATT, qn_t_w, kn_t_w, cos_t, sin_t);
    bgemm<2><<<gp, 128, BG_SMEM>>>(ATT, WPT, proj_t_b, X, X, MODS + 5 * DD, MTOK, DD, DD);

    // ---- MLP (SiLU-GLU fused into w12 GEMM epilogue) ----
    rmsnorm_mod_kernel<<<MTOK, 256>>>(X, XN, norm3_w, MODS, 6, 7, 0);
    bgemm<3><<<g12, 128, BG_SMEM>>>(XN, W12I, W12B, (float*)H, nullptr, nullptr, MTOK, W12P, DD);
    bgemm<1><<<gp, 128, BG_SMEM>>>(H, W3P, w3_b, out, X, MODS + 8 * DD, MTOK, DD, HFFP);
}

// round 17
// speedup vs baseline: 1.1021x; 1.0072x over previous
#include <cuda_runtime.h>
#include <cuda_bf16.h>
#include <cstdint>
#include <math.h>

// ---------------- problem constants ----------------
#define DD    1024
#define NHEADS 16
#define HDIM  64
#define BSZ   2
#define TT    16
#define LLEN  256
#define MTOK  8192          // B*T*L
#define HFF   2730
#define HFFP  2752          // padded (= 43*64)
#define W12P  5504          // 2*HFFP interleaved output width
#define QKVN  3072
#define MODN  9216          // 9*D

// ---------------- device scratch (allocation-free rule) ----------------
__device__ float g_X  [(size_t)MTOK * DD];
__device__ float g_MODS[BSZ * MODN];
__device__ float g_SC  [BSZ * DD];
__device__ float g_W12B[W12P];
// bf16 buffers
__device__ __nv_bfloat16 g_QKV[(size_t)MTOK * QKVN];
__device__ __nv_bfloat16 g_XN [(size_t)MTOK * DD];
__device__ __nv_bfloat16 g_ATT[(size_t)MTOK * DD];
__device__ __nv_bfloat16 g_H  [(size_t)MTOK * HFFP];
__device__ __nv_bfloat16 g_W3P[(size_t)DD * HFFP];
__device__ __nv_bfloat16 g_WQS[(size_t)QKVN * DD];
__device__ __nv_bfloat16 g_WPS[(size_t)DD * DD];
__device__ __nv_bfloat16 g_WQT[(size_t)QKVN * DD];
__device__ __nv_bfloat16 g_WPT[(size_t)DD * DD];
__device__ __nv_bfloat16 g_W12I[(size_t)W12P * DD];

// ---------------- PTX helpers ----------------
__device__ __forceinline__ void cp16(uint32_t s, const void* g) {
    asm volatile("cp.async.cg.shared.global [%0], [%1], 16;\n" :: "r"(s), "l"(g));
}
__device__ __forceinline__ void cp_commit() { asm volatile("cp.async.commit_group;\n"); }
__device__ __forceinline__ void cp_wait1()  { asm volatile("cp.async.wait_group 1;\n"); }

#define LDSM4(r0, r1, r2, r3, addr) \
    asm volatile("ldmatrix.sync.aligned.m8n8.x4.shared.b16 {%0,%1,%2,%3}, [%4];" \
        : "=r"(r0), "=r"(r1), "=r"(r2), "=r"(r3) : "r"(addr))

typedef unsigned long long u64t;
__device__ __forceinline__ u64t pk2(float lo, float hi) {
    u64t r; asm("mov.b64 %0, {%1,%2};" : "=l"(r) : "f"(lo), "f"(hi)); return r;
}
__device__ __forceinline__ u64t fma2_(u64t a, u64t b, u64t c) {
    u64t d; asm("fma.rn.f32x2 %0,%1,%2,%3;" : "=l"(d) : "l"(a), "l"(b), "l"(c)); return d;
}
__device__ __forceinline__ float2 upk2(u64t v) {
    float2 f; asm("mov.b64 {%0,%1}, %2;" : "=f"(f.x), "=f"(f.y) : "l"(v)); return f;
}
// 4 consecutive bf16 (as uint2) -> float4
__device__ __forceinline__ float4 bf4_to_f4(uint2 u) {
    __nv_bfloat162 a = *reinterpret_cast<__nv_bfloat162*>(&u.x);
    __nv_bfloat162 b = *reinterpret_cast<__nv_bfloat162*>(&u.y);
    float2 fa = __bfloat1622float2(a);
    float2 fb = __bfloat1622float2(b);
    return make_float4(fa.x, fa.y, fb.x, fb.y);
}

// ---------------- merged weight-prep kernel (single launch) ----------------
#define WPREP_R0 (QKVN * DD / 4)
#define WPREP_R1 (WPREP_R0 + DD * DD / 4)
#define WPREP_R2 (WPREP_R1 + QKVN * DD / 4)
#define WPREP_R3 (WPREP_R2 + DD * DD / 4)
#define WPREP_R4 (WPREP_R3 + W12P * (DD / 2))
#define WPREP_R5 (WPREP_R4 + DD * (HFFP / 2))

__device__ __forceinline__ void cvt4(const float4* src, __nv_bfloat162* dst, int i) {
    float4 v = src[i];
    dst[2 * i]     = __floats2bfloat162_rn(v.x, v.y);
    dst[2 * i + 1] = __floats2bfloat162_rn(v.z, v.w);
}

__global__ void wprep_kernel(const float4* __restrict__ qs, const float4* __restrict__ ps,
                             const float4* __restrict__ qt, const float4* __restrict__ pt,
                             const float* __restrict__ w12w, const float* __restrict__ w12b,
                             const float* __restrict__ w3,
                             __nv_bfloat162* __restrict__ WQS, __nv_bfloat162* __restrict__ WPS,
                             __nv_bfloat162* __restrict__ WQT, __nv_bfloat162* __restrict__ WPT,
                             __nv_bfloat162* __restrict__ W12I, float* __restrict__ BI,
                             __nv_bfloat162* __restrict__ W3P) {
    int idx = blockIdx.x * 256 + threadIdx.x;
    if (idx < WPREP_R0) {
        cvt4(qs, WQS, idx);
    } else if (idx < WPREP_R1) {
        cvt4(ps, WPS, idx - WPREP_R0);
    } else if (idx < WPREP_R2) {
        cvt4(qt, WQT, idx - WPREP_R1);
    } else if (idx < WPREP_R3) {
        cvt4(pt, WPT, idx - WPREP_R2);
    } else if (idx < WPREP_R4) {
        int u = idx - WPREP_R3;                 // over W12P * DD/2
        int n = u / (DD / 2);
        int k = (u % (DD / 2)) * 2;
        int j = n >> 1, s = n & 1;
        float a = 0.f, b = 0.f;
        if (j < HFF) {
            const float* src = w12w + (size_t)(j + s * HFF) * DD + k;
            a = src[0]; b = src[1];
        }
        W12I[u] = __floats2bfloat162_rn(a, b);
        if (k == 0) BI[n] = (j < HFF) ? w12b[j + s * HFF] : 0.f;
    } else if (idx < WPREP_R5) {
        int u = idx - WPREP_R4;                 // over DD * HFFP/2
        int n = u / (HFFP / 2), kp = u % (HFFP / 2);
        int k = kp * 2;
        float a = (k < HFF) ? w3[(size_t)n * HFF + k] : 0.f;
        float b = (k < HFF) ? w3[(size_t)n * HFF + k + 1] : 0.f;
        W3P[u] = __floats2bfloat162_rn(a, b);
    }
}

// ---------------- small utility kernels ----------------
__global__ void siluc_kernel(const float* __restrict__ c, float* __restrict__ out) {
    int i = blockIdx.x * 256 + threadIdx.x;
    if (i < BSZ * DD) {
        float v = c[i];
        out[i] = v / (1.f + expf(-v));
    }
}

// mods = silu(c) @ ada_w.T + ada_b   -> (B, 9*D)   (tiny, fp32 exact)
__global__ void mods_kernel(const float* __restrict__ sc, const float* __restrict__ aw,
                            const float* __restrict__ ab, float* __restrict__ mods) {
    int gw = (blockIdx.x * blockDim.x + threadIdx.x) >> 5;
    int lane = threadIdx.x & 31;
    if (gw >= BSZ * MODN) return;
    int b = gw / MODN, n = gw % MODN;
    const float4* cv = (const float4*)(sc + b * DD);
    const float4* wv = (const float4*)(aw + (size_t)n * DD);
    float s = 0.f;
#pragma unroll
    for (int k = 0; k < 8; k++) {
        float4 a = cv[lane + k * 32];
        float4 w = wv[lane + k * 32];
        s += a.x * w.x + a.y * w.y + a.z * w.z + a.w * w.w;
    }
#pragma unroll
    for (int o = 16; o > 0; o >>= 1) s += __shfl_down_sync(0xffffffffu, s, o);
    if (lane == 0) mods[gw] = s + ab[n];
}

// rmsnorm + adaLN modulation -> bf16.  One warp per row (no barriers).
__global__ void rmsnorm_mod_kernel(const float* __restrict__ X, __nv_bfloat16* __restrict__ XN,
                                   const float* __restrict__ w, const float* __restrict__ mods,
                                   int shIdx, int scIdx, int gatherT) {
    int wid = threadIdx.x >> 5, lane = threadIdx.x & 31;
    int m = blockIdx.x * 8 + wid;
    int b = m >> 12;
    int srcRow = m;
    if (gatherT) {
        int rem = m & 4095;
        int l = rem >> 4;
        int t = rem & 15;
        srcRow = (b * TT + t) * LLEN + l;
    }
    const float4* xr = (const float4*)(X + (size_t)srcRow * DD);
    float4 v[8];
    float ss = 0.f;
#pragma unroll
    for (int k = 0; k < 8; k++) {
        v[k] = xr[lane + 32 * k];
        ss += v[k].x * v[k].x + v[k].y * v[k].y + v[k].z * v[k].z + v[k].w * v[k].w;
    }
#pragma unroll
    for (int o = 16; o > 0; o >>= 1) ss += __shfl_xor_sync(0xffffffffu, ss, o);
    float r = rsqrtf(ss * (1.f / 1024.f) + 1e-6f);
    const float4* wp  = (const float4*)w;
    const float4* shp = (const float4*)(mods + (b * 9 + shIdx) * DD);
    const float4* scp = (const float4*)(mods + (b * 9 + scIdx) * DD);
    __nv_bfloat162* row = (__nv_bfloat162*)(XN + (size_t)m * DD);
#pragma unroll
    for (int k = 0; k < 8; k++) {
        int d4 = lane + 32 * k;
        float4 w4 = wp[d4], sh4 = shp[d4], sc4 = scp[d4];
        float o0 = v[k].x * r * w4.x * (1.f + sc4.x) + sh4.x;
        float o1 = v[k].y * r * w4.y * (1.f + sc4.y) + sh4.y;
        float o2 = v[k].z * r * w4.z * (1.f + sc4.z) + sh4.z;
        float o3 = v[k].w * r * w4.w * (1.f + sc4.w) + sh4.w;
        row[2 * d4]     = __floats2bfloat162_rn(o0, o1);
        row[2 * d4 + 1] = __floats2bfloat162_rn(o2, o3);
    }
}

// ---------------- attention: fused qk-rmsnorm + RoPE, plain-exp softmax ----------------
// QKV arrives bf16; 16-byte staging loads; hot loop stays fp32 f32x2.
template <int SEQ, int BH>
__global__ __launch_bounds__(256, 1) void attn_kernel(const __nv_bfloat16* __restrict__ QKV,
                                                      __nv_bfloat16* __restrict__ ATT,
                                                      const float* __restrict__ qw,
                                                      const float* __restrict__ kw,
                                                      const float* __restrict__ ct,
                                                      const float* __restrict__ st) {
    extern __shared__ float4 sm4[];
    float4* ks = sm4;                      // [BH][SEQ][16]
    float4* vs = sm4 + BH * SEQ * 16;
    int tid = threadIdx.x;
    int unit0 = blockIdx.x * BH;

    for (int i = tid; i < BH * SEQ * 8; i += 256) {
        int u = i / (SEQ * 8);
        int rem = i % (SEQ * 8);
        int j = rem / 8, d8 = rem % 8;
        int bh = unit0 + u;
        int batch = bh >> 4, head = bh & 15;
        const __nv_bfloat16* base = QKV + (size_t)(batch * SEQ + j) * QKVN + head * HDIM;
        uint4 kk = ((const uint4*)(base + DD))[d8];
        uint4 vv = ((const uint4*)(base + 2 * DD))[d8];
        int o = (u * SEQ + j) * 16 + d8 * 2;
        ks[o]     = bf4_to_f4(make_uint2(kk.x, kk.y));
        ks[o + 1] = bf4_to_f4(make_uint2(kk.z, kk.w));
        vs[o]     = bf4_to_f4(make_uint2(vv.x, vv.y));
        vs[o + 1] = bf4_to_f4(make_uint2(vv.z, vv.w));
    }
    __syncthreads();

    // ---- K rows: rmsnorm(kw) + rope, in SMEM (1 row per thread) ----
    {
        float4* kr = ks + tid * 16;
        int posk = tid % SEQ;
        float4 kv[16];
        float s = 0.f;
#pragma unroll
        for (int i = 0; i < 16; i++) {
            kv[i] = kr[i];
            s += kv[i].x * kv[i].x + kv[i].y * kv[i].y + kv[i].z * kv[i].z + kv[i].w * kv[i].w;
        }
        float r = rsqrtf(s * (1.f / 64.f) + 1e-6f);
        const float4* w4 = (const float4*)kw;
        const float4* c4 = (const float4*)(ct + posk * 64);
        const float4* s4 = (const float4*)(st + posk * 64);
        float4 kn[16];
#pragma unroll
        for (int i = 0; i < 16; i++) {
            float4 ww = w4[i];
            kn[i] = make_float4(kv[i].x * r * ww.x, kv[i].y * r * ww.y,
                                kv[i].z * r * ww.z, kv[i].w * r * ww.w);
        }
#pragma unroll
        for (int i = 0; i < 8; i++) {
            float4 ca = c4[i], sa = s4[i], cb = c4[i + 8], sb = s4[i + 8];
            float4 lo = kn[i], hi = kn[i + 8];
            kr[i]     = make_float4(lo.x * ca.x - hi.x * sa.x, lo.y * ca.y - hi.y * sa.y,
                                    lo.z * ca.z - hi.z * sa.z, lo.w * ca.w - hi.w * sa.w);
            kr[i + 8] = make_float4(hi.x * cb.x + lo.x * sb.x, hi.y * cb.y + lo.y * sb.y,
                                    hi.z * cb.z + lo.z * sb.z, hi.w * cb.w + lo.w * sb.w);
        }
    }
    __syncthreads();

    int u = tid / SEQ, qi = tid % SEQ;
    int bh = unit0 + u;
    int batch = bh >> 4, head = bh & 15;
    const uint2* qp = (const uint2*)(QKV + (size_t)(batch * SEQ + qi) * QKVN + head * HDIM);
    u64t q2[32];
    {
        float4 q[16];
        float s = 0.f;
#pragma unroll
        for (int i = 0; i < 16; i++) {
            q[i] = bf4_to_f4(qp[i]);
            s += q[i].x * q[i].x + q[i].y * q[i].y + q[i].z * q[i].z + q[i].w * q[i].w;
        }
        float r = rsqrtf(s * (1.f / 64.f) + 1e-6f);
        const float4* w4 = (const float4*)qw;
        const float4* c4 = (const float4*)(ct + qi * 64);
        const float4* s4 = (const float4*)(st + qi * 64);
        float4 qn[16];
#pragma unroll
        for (int i = 0; i < 16; i++) {
            float4 ww = w4[i];
            qn[i] = make_float4(q[i].x * r * ww.x, q[i].y * r * ww.y,
                                q[i].z * r * ww.z, q[i].w * r * ww.w);
        }
#pragma unroll
        for (int i = 0; i < 8; i++) {
            float4 ca = c4[i], sa = s4[i], cb = c4[i + 8], sb = s4[i + 8];
            float4 lo = qn[i], hi = qn[i + 8];
            float4 e0 = make_float4(lo.x * ca.x - hi.x * sa.x, lo.y * ca.y - hi.y * sa.y,
                                    lo.z * ca.z - hi.z * sa.z, lo.w * ca.w - hi.w * sa.w);
            float4 e1 = make_float4(hi.x * cb.x + lo.x * sb.x, hi.y * cb.y + lo.y * sb.y,
                                    hi.z * cb.z + lo.z * sb.z, hi.w * cb.w + lo.w * sb.w);
            q2[2 * i]          = pk2(e0.x, e0.y);
            q2[2 * i + 1]      = pk2(e0.z, e0.w);
            q2[2 * (i + 8)]     = pk2(e1.x, e1.y);
            q2[2 * (i + 8) + 1] = pk2(e1.z, e1.w);
        }
    }

    const u64t z2 = pk2(0.f, 0.f);
    u64t o2[32];
#pragma unroll
    for (int i = 0; i < 32; i++) o2[i] = z2;

    float lsum = 0.f;
    const double2* kr2 = (const double2*)(ks + u * SEQ * 16);   // 16B vectors
    const double2* vr2 = (const double2*)(vs + u * SEQ * 16);
    for (int j = 0; j < SEQ; j++) {
        const double2* kj = kr2 + j * 16;
        u64t a0 = z2, a1 = z2, a2 = z2, a3 = z2;
#pragma unroll
        for (int i = 0; i < 8; i++) {
            double2 t0 = kj[2 * i];
            double2 t1 = kj[2 * i + 1];
            a0 = fma2_(q2[4 * i + 0], (u64t)__double_as_longlong(t0.x), a0);
            a1 = fma2_(q2[4 * i + 1], (u64t)__double_as_longlong(t0.y), a1);
            a2 = fma2_(q2[4 * i + 2], (u64t)__double_as_longlong(t1.x), a2);
            a3 = fma2_(q2[4 * i + 3], (u64t)__double_as_longlong(t1.y), a3);
        }
        float2 f0 = upk2(a0), f1 = upk2(a1), f2 = upk2(a2), f3 = upk2(a3);
        float s = ((f0.x + f0.y) + (f1.x + f1.y)) + ((f2.x + f2.y) + (f3.x + f3.y));
        float p = __expf(s * 0.125f);
        lsum += p;
        u64t p2 = pk2(p, p);
        const double2* vj = vr2 + j * 16;
#pragma unroll
        for (int i = 0; i < 16; i++) {
            double2 t = vj[i];
            o2[2 * i]     = fma2_(p2, (u64t)__double_as_longlong(t.x), o2[2 * i]);
            o2[2 * i + 1] = fma2_(p2, (u64t)__double_as_longlong(t.y), o2[2 * i + 1]);
        }
    }
    float inv = 1.f / lsum;
    __nv_bfloat162* op = (__nv_bfloat162*)(ATT + (size_t)(batch * SEQ + qi) * DD + head * HDIM);
#pragma unroll
    for (int i = 0; i < 32; i++) {
        float2 f = upk2(o2[i]);
        op[i] = __floats2bfloat162_rn(f.x * inv, f.y * inv);
    }
}

// ---------------- bf16 tensor-core GEMM (ldmatrix, K=32 x 3-stage ring, 2 CTA/SM) ----------------
// C = A(MxK) * B(NxK)^T + epilogue.  Requires M % 128 == 0, N % 128 == 0, K % 32 == 0.
// EPI 1: C[m,n] = resid[m,n] + gate[b,n]*(acc+bias)     (N==1024)
// EPI 2: like 1, scattered through (B,L,T)->(B,T,L)      (N==1024)
// EPI 3: fused SiLU-GLU: pairs (2j,2j+1)=(h1,h2) -> bf16 H[m,j], row stride HFFP
// EPI 4: bf16 output with bias (QKV)
#define BG_STG 10240           // 128 rows * 80 bytes (32 bf16 data + 8 pad)
#define BG_B_OFF (3 * BG_STG)  // 30720
#define BG_SMEM (6 * BG_STG)   // 61440

template <int EPI>
__global__ __launch_bounds__(128, 2) void bgemm(const __nv_bfloat16* __restrict__ A,
                                                const __nv_bfloat16* __restrict__ Bw,
                                                const float* __restrict__ bias,
                                                float* __restrict__ C,
                                                const float* __restrict__ resid,
                                                const float* __restrict__ gate,
                                                int M, int N, int K) {
    extern __shared__ char smem[];
    const int tid = threadIdx.x;
    const int wid = tid >> 5, lane = tid & 31;
    const int g = lane >> 2, t = lane & 3;
    const int wm0 = (wid >> 1) * 64, wn0 = (wid & 1) * 64;
    const int m0 = blockIdx.y * 128, n0 = blockIdx.x * 128;

    const __nv_bfloat16* aRow = A + (size_t)(m0 + tid) * K;
    const __nv_bfloat16* bRow = Bw + (size_t)(n0 + tid) * K;
    const uint32_t smemBase = (uint32_t)__cvta_generic_to_shared(smem);
    const uint32_t aBase = smemBase + tid * 80;
    const uint32_t bBase = aBase + BG_B_OFF;

    // ldmatrix per-thread fragment addresses (within a stage)
    const uint32_t aFrag = smemBase + (wm0 + (lane & 15)) * 80 + (lane >> 4) * 16;
    const uint32_t bFrag = smemBase + BG_B_OFF
                         + (wn0 + (lane & 7) + ((lane >> 4) & 1) * 8) * 80
                         + ((lane >> 3) & 1) * 16;

    float acc[4][8][4];
#pragma unroll
    for (int i = 0; i < 4; i++)
#pragma unroll
        for (int j = 0; j < 8; j++)
#pragma unroll
            for (int r = 0; r < 4; r++) acc[i][j][r] = 0.f;

    const int ntiles = K >> 5;

    // prologue: prefetch tiles 0,1
#pragma unroll
    for (int p = 0; p < 2; p++) {
        int kt = p * 32;
#pragma unroll
        for (int q = 0; q < 4; q++) cp16(aBase + p * BG_STG + q * 16, aRow + kt + q * 8);
#pragma unroll
        for (int q = 0; q < 4; q++) cp16(bBase + p * BG_STG + q * 16, bRow + kt + q * 8);
        cp_commit();
    }

    for (int tt = 0; tt < ntiles; tt++) {
        cp_wait1();
        __syncthreads();

        // prefetch tile tt+2 into slot (tt+2)%3
        if (tt + 2 < ntiles) {
            int slot = (tt + 2) % 3;
            int kt = (tt + 2) * 32;
#pragma unroll
            for (int q = 0; q < 4; q++) cp16(aBase + slot * BG_STG + q * 16, aRow + kt + q * 8);
#pragma unroll
            for (int q = 0; q < 4; q++) cp16(bBase + slot * BG_STG + q * 16, bRow + kt + q * 8);
        }
        cp_commit();

        // compute from slot tt%3 via ldmatrix
        const uint32_t aS = aFrag + (tt % 3) * BG_STG;
        const uint32_t bS = bFrag + (tt % 3) * BG_STG;
#pragma unroll
        for (int ks = 0; ks < 2; ks++) {
            uint32_t a[4][4], b[8][2];
#pragma unroll
            for (int i = 0; i < 4; i++)
                LDSM4(a[i][0], a[i][1], a[i][2], a[i][3], aS + i * (16 * 80) + ks * 32);
#pragma unroll
            for (int jj = 0; jj < 4; jj++)
                LDSM4(b[2 * jj][0], b[2 * jj][1], b[2 * jj + 1][0], b[2 * jj + 1][1],
                      bS + jj * (16 * 80) + ks * 32);
#pragma unroll
            for (int i = 0; i < 4; i++)
#pragma unroll
                for (int j = 0; j < 8; j++) {
                    asm volatile(
                        "mma.sync.aligned.m16n8k16.row.col.f32.bf16.bf16.f32 "
                        "{%0,%1,%2,%3},{%4,%5,%6,%7},{%8,%9},{%0,%1,%2,%3};\n"
                        : "+f"(acc[i][j][0]), "+f"(acc[i][j][1]),
                          "+f"(acc[i][j][2]), "+f"(acc[i][j][3])
                        : "r"(a[i][0]), "r"(a[i][1]), "r"(a[i][2]), "r"(a[i][3]),
                          "r"(b[j][0]), "r"(b[j][1]));
                }
        }
        // no trailing __syncthreads(): next iteration's top sync provides the ordering
    }

    // epilogue.  batch index is constant per tile (4096 % 128 == 0).
    const int bb = m0 >> 12;
#pragma unroll
    for (int j = 0; j < 8; j++) {
        const int nc = n0 + wn0 + 8 * j + 2 * t;
        const float b0 = bias[nc], b1 = bias[nc + 1];
        float g0, g1;
        if (EPI == 1 || EPI == 2) {
            g0 = gate[bb * MODN + nc];
            g1 = gate[bb * MODN + nc + 1];
        }
#pragma unroll
        for (int i = 0; i < 4; i++) {
            int mr = m0 + wm0 + 16 * i + g;
#pragma unroll
            for (int h = 0; h < 2; h++) {
                int m = mr + h * 8;
                float v0 = acc[i][j][2 * h + 0] + b0;
                float v1 = acc[i][j][2 * h + 1] + b1;
                if (EPI == 1) {
                    size_t idx = (size_t)m * N + nc;
                    float2 rr = *(const float2*)(resid + idx);
                    *(float2*)(C + idx) = make_float2(rr.x + g0 * v0, rr.y + g1 * v1);
                } else if (EPI == 2) {
                    int rem = m & 4095;
                    int l = rem >> 4;
                    int ti = rem & 15;
                    size_t idx = ((size_t)((bb * TT + ti) * LLEN + l)) * N + nc;
                    float2 rr = *(const float2*)(resid + idx);
                    *(float2*)(C + idx) = make_float2(rr.x + g0 * v0, rr.y + g1 * v1);
                } else if (EPI == 3) {  // fused SiLU-GLU, interleaved pairs -> bf16 H
                    int pj = nc >> 1;
                    float hh = 0.f;
                    if (pj < HFF) {
                        float e = __expf(-v0);
                        hh = __fdividef(v0, 1.f + e) * v1;
                    }
                    ((__nv_bfloat16*)C)[(size_t)m * HFFP + pj] = __float2bfloat16(hh);
                } else {  // EPI == 4: bf16 output with bias (QKV)
                    ((__nv_bfloat162*)C)[((size_t)m * N + nc) >> 1] = __floats2bfloat162_rn(v0, v1);
                }
            }
        }
    }
}

// ---------------- host orchestration ----------------
extern "C" void kernel_launch(void* const* d_in, const int* in_sizes, int n_in,
                              void* d_out, int out_size) {
    const float* x       = (const float*)d_in[0];
    const float* c       = (const float*)d_in[1];
    const float* cos_s   = (const float*)d_in[2];
    const float* sin_s   = (const float*)d_in[3];
    const float* cos_t   = (const float*)d_in[4];
    const float* sin_t   = (const float*)d_in[5];
    const float* norm1_w = (const float*)d_in[6];
    const float* norm2_w = (const float*)d_in[7];
    const float* norm3_w = (const float*)d_in[8];
    const float* qkv_s_w = (const float*)d_in[9];
    const float* qkv_s_b = (const float*)d_in[10];
    const float* qn_s_w  = (const float*)d_in[11];
    const float* kn_s_w  = (const float*)d_in[12];
    const float* proj_s_w= (const float*)d_in[13];
    const float* proj_s_b= (const float*)d_in[14];
    const float* qkv_t_w = (const float*)d_in[15];
    const float* qkv_t_b = (const float*)d_in[16];
    const float* qn_t_w  = (const float*)d_in[17];
    const float* kn_t_w  = (const float*)d_in[18];
    const float* proj_t_w= (const float*)d_in[19];
    const float* proj_t_b= (const float*)d_in[20];
    const float* w12_w   = (const float*)d_in[21];
    const float* w12_b   = (const float*)d_in[22];
    const float* w3_w    = (const float*)d_in[23];
    const float* w3_b    = (const float*)d_in[24];
    const float* ada_w   = (const float*)d_in[25];
    const float* ada_b   = (const float*)d_in[26];
    float* out = (float*)d_out;

    float *X, *MODS, *SC, *W12B;
    __nv_bfloat16 *QKV, *XN, *ATT, *H, *W3P, *WQS, *WPS, *WQT, *WPT, *W12I;
    cudaGetSymbolAddress((void**)&X,   g_X);
    cudaGetSymbolAddress((void**)&MODS,g_MODS);
    cudaGetSymbolAddress((void**)&SC,  g_SC);
    cudaGetSymbolAddress((void**)&W12B,g_W12B);
    cudaGetSymbolAddress((void**)&QKV, g_QKV);
    cudaGetSymbolAddress((void**)&XN,  g_XN);
    cudaGetSymbolAddress((void**)&ATT, g_ATT);
    cudaGetSymbolAddress((void**)&H,   g_H);
    cudaGetSymbolAddress((void**)&W3P, g_W3P);
    cudaGetSymbolAddress((void**)&WQS, g_WQS);
    cudaGetSymbolAddress((void**)&WPS, g_WPS);
    cudaGetSymbolAddress((void**)&WQT, g_WQT);
    cudaGetSymbolAddress((void**)&WPT, g_WPT);
    cudaGetSymbolAddress((void**)&W12I,g_W12I);

    cudaFuncSetAttribute(attn_kernel<256, 1>, cudaFuncAttributeMaxDynamicSharedMemorySize, 131072);
    cudaFuncSetAttribute(attn_kernel<16, 16>, cudaFuncAttributeMaxDynamicSharedMemorySize, 131072);
    cudaFuncSetAttribute(bgemm<1>, cudaFuncAttributeMaxDynamicSharedMemorySize, BG_SMEM);
    cudaFuncSetAttribute(bgemm<2>, cudaFuncAttributeMaxDynamicSharedMemorySize, BG_SMEM);
    cudaFuncSetAttribute(bgemm<3>, cudaFuncAttributeMaxDynamicSharedMemorySize, BG_SMEM);
    cudaFuncSetAttribute(bgemm<4>, cudaFuncAttributeMaxDynamicSharedMemorySize, BG_SMEM);

    // init + merged weight conversion (single launch)
    siluc_kernel<<<(BSZ * DD + 255) / 256, 256>>>(c, SC);
    mods_kernel<<<BSZ * MODN / 8, 256>>>(SC, ada_w, ada_b, MODS);
    wprep_kernel<<<(WPREP_R5 + 255) / 256, 256>>>(
        (const float4*)qkv_s_w, (const float4*)proj_s_w,
        (const float4*)qkv_t_w, (const float4*)proj_t_w,
        w12_w, w12_b, w3_w,
        (__nv_bfloat162*)WQS, (__nv_bfloat162*)WPS,
        (__nv_bfloat162*)WQT, (__nv_bfloat162*)WPT,
        (__nv_bfloat162*)W12I, W12B, (__nv_bfloat162*)W3P);

    dim3 gq(QKVN / 128, MTOK / 128);
    dim3 gp(DD / 128, MTOK / 128);
    dim3 g12(W12P / 128, MTOK / 128);

    // ---- spatial attention branch (residual read straight from input x) ----
    rmsnorm_mod_kernel<<<MTOK / 8, 256>>>(x, XN, norm1_w, MODS, 0, 1, 0);
    bgemm<4><<<gq, 128, BG_SMEM>>>(XN, WQS, qkv_s_b, (float*)QKV, nullptr, nullptr, MTOK, QKVN, DD);
    attn_kernel<256, 1><<<BSZ * TT * NHEADS, 256, 131072>>>(QKV, ATT, qn_s_w, kn_s_w, cos_s, sin_s);
    bgemm<1><<<gp, 128, BG_SMEM>>>(ATT, WPS, proj_s_b, X, x, MODS + 2 * DD, MTOK, DD, DD);

    // ---- temporal attention branch ----
    rmsnorm_mod_kernel<<<MTOK / 8, 256>>>(X, XN, norm2_w, MODS, 3, 4, 1);
    bgemm<4><<<gq, 128, BG_SMEM>>>(XN, WQT, qkv_t_b, (float*)QKV, nullptr, nullptr, MTOK, QKVN, DD);
    attn_kernel<16, 16><<<BSZ * LLEN * NHEADS / 16, 256, 131072>>>(QKV, ATT, qn_t_w, kn_t_w, cos_t, sin_t);
    bgemm<2><<<gp, 128, BG_SMEM>>>(ATT, WPT, proj_t_b, X, X, MODS + 5 * DD, MTOK, DD, DD);

    // ---- MLP (SiLU-GLU fused into w12 GEMM epilogue) ----
    rmsnorm_mod_kernel<<<MTOK / 8, 256>>>(X, XN, norm3_w, MODS, 6, 7, 0);
    bgemm<3><<<g12, 128, BG_SMEM>>>(XN, W12I, W12B, (float*)H, nullptr, nullptr, MTOK, W12P, DD);
    bgemm<1><<<gp, 128, BG_SMEM>>>(H, W3P, w3_b, out, X, MODS + 8 * DD, MTOK, DD, HFFP);
}